// round 15
// baseline (speedup 1.0000x reference)
#include <cuda_runtime.h>
#include <cuda_bf16.h>
#include <math.h>
#include <stdint.h>

// ---------------- problem constants ----------------
#define T_TOK 4096
#define DIM   1024
#define SEQ   1024
#define NB    4
#define NH    16
#define NKVH  4
#define HD    64
#define NE    8
#define FF    2816
#define NCOMP 256
#define QKVN  1536
#define MAXR  9216
#define MAXTILES 72

typedef __nv_bfloat16 bf16;
typedef __nv_bfloat162 bf162;
typedef unsigned long long u64;

struct bf16x4 { bf162 a, b; };

// ---------------- scratch (device globals) ----------------
__device__ float g_h1[(size_t)T_TOK * DIM];
__device__ float g_h1buf[(size_t)MAXR * FF];
__device__ float g_moe[(size_t)MAXR * DIM];

__device__ bf16 g_qxh[(size_t)T_TOK * QKVN], g_qxl[(size_t)T_TOK * QKVN];
__device__ bf16 g_xnh[(size_t)T_TOK * DIM],  g_xnl[(size_t)T_TOK * DIM];
__device__ bf16 g_atth[(size_t)T_TOK * DIM], g_attl[(size_t)T_TOK * DIM];
__device__ bf16 g_prevh[(size_t)T_TOK * DIM],g_prevl[(size_t)T_TOK * DIM];
__device__ bf16 g_h2h[(size_t)T_TOK * DIM],  g_h2l[(size_t)T_TOK * DIM];
__device__ bf16 g_acth[(size_t)MAXR * FF];
__device__ bf16 g_outhh[(size_t)T_TOK * DIM],g_outhl[(size_t)T_TOK * DIM];

// weights [K][N] layout
__device__ bf16 g_wqkvh[(size_t)DIM * QKVN], g_wqkvl[(size_t)DIM * QKVN];
__device__ bf16 g_woh[(size_t)DIM * DIM],    g_wol[(size_t)DIM * DIM];
__device__ bf16 g_mixtoph[(size_t)DIM * DIM], g_mixtopl[(size_t)DIM * DIM];
__device__ bf16 g_mixeffh[(size_t)2 * DIM * DIM], g_mixeffl[(size_t)2 * DIM * DIM];
__device__ bf16 g_w1h[(size_t)NE * DIM * FF];       // hi-only (bf16 MoE)
__device__ bf16 g_w2h[(size_t)NE * FF * DIM];
__device__ bf16 g_w3h[(size_t)NE * DIM * FF];
__device__ bf16 g_cwh[(size_t)DIM * NCOMP],  g_cwl[(size_t)DIM * NCOMP];

__device__ int   g_expsel[T_TOK * 2];
__device__ float g_expw[T_TOK * 2];
__device__ int   g_cnt[NE];
__device__ int   g_fill[NE];
__device__ int   g_pstart[NE];
__device__ int   g_rows_token[MAXR];
__device__ int   g_tok_rowpos[T_TOK * 2];
__device__ int   g_tile_expert[MAXTILES];

// ---------------- asm helpers ----------------
__device__ __forceinline__ uint32_t saddr(const void* p) {
    return (uint32_t)__cvta_generic_to_shared(p);
}
__device__ __forceinline__ void cp16(uint32_t s, const void* g) {
    asm volatile("cp.async.cg.shared.global [%0], [%1], 16;\n" :: "r"(s), "l"(g));
}
__device__ __forceinline__ void cp_commit() { asm volatile("cp.async.commit_group;\n"); }
template<int N> __device__ __forceinline__ void cp_wait() {
    asm volatile("cp.async.wait_group %0;\n" :: "n"(N));
}
__device__ __forceinline__ void ldsm4(uint32_t a, uint32_t* r) {
    asm volatile("ldmatrix.sync.aligned.m8n8.x4.shared.b16 {%0,%1,%2,%3}, [%4];\n"
                 : "=r"(r[0]), "=r"(r[1]), "=r"(r[2]), "=r"(r[3]) : "r"(a));
}
__device__ __forceinline__ void ldsm4t(uint32_t a, uint32_t& r0, uint32_t& r1, uint32_t& r2, uint32_t& r3) {
    asm volatile("ldmatrix.sync.aligned.m8n8.x4.trans.shared.b16 {%0,%1,%2,%3}, [%4];\n"
                 : "=r"(r0), "=r"(r1), "=r"(r2), "=r"(r3) : "r"(a));
}
__device__ __forceinline__ void mma_bf16(float c[4], const uint32_t a[4], const uint32_t b[2]) {
    asm volatile("mma.sync.aligned.m16n8k16.row.col.f32.bf16.bf16.f32 "
                 "{%0,%1,%2,%3}, {%4,%5,%6,%7}, {%8,%9}, {%0,%1,%2,%3};\n"
                 : "+f"(c[0]), "+f"(c[1]), "+f"(c[2]), "+f"(c[3])
                 : "r"(a[0]), "r"(a[1]), "r"(a[2]), "r"(a[3]), "r"(b[0]), "r"(b[1]));
}

// ---------------- smem geometry (GEMM) ----------------
// TERMS=3 (K-step 32): A hi+lo (stride 40) + B hi+lo (stride 136), 3 stages.
#define ARS3 40
#define APL3 (128 * ARS3 * 2)       // 10240
#define BPL3 (32 * 136 * 2)         // 8704
#define STAGE_G3 (2 * APL3 + 2 * BPL3)   // 37888
#define SMEM_G3  (3 * STAGE_G3)          // 113664 -> 2 CTAs/SM
// TERMS=1 (K-step 64): A hi (stride 72) + B hi, 3 stages.
#define ARS1 72
#define APL1 (128 * ARS1 * 2)       // 18432
#define BPL1 (64 * 136 * 2)         // 17408
#define STAGE_G1 (APL1 + BPL1)      // 35840
#define SMEM_G1  (3 * STAGE_G1)     // 107520 -> 2 CTAs/SM

// attention smem
#define ATQ_PL  18432
#define ATQ_SZ  (2 * ATQ_PL)
#define AT_PL   9216
#define AT_BUF  (4 * AT_PL)
#define SMEM_AT (ATQ_SZ + 2 * AT_BUF)  // 110592 -> 2 CTAs/SM

// ---------------- split helpers ----------------
__device__ __forceinline__ void split_store(bf16* hi, bf16* lo, size_t idx, float v0, float v1) {
    bf162 h2, l2;
    h2.x = __float2bfloat16(v0); h2.y = __float2bfloat16(v1);
    l2.x = __float2bfloat16(v0 - __bfloat162float(h2.x));
    l2.y = __float2bfloat16(v1 - __bfloat162float(h2.y));
    *(bf162*)&hi[idx] = h2;
    *(bf162*)&lo[idx] = l2;
}
__device__ __forceinline__ void split4_store(bf16* hi, bf16* lo, size_t idx, float4 v) {
    bf16x4 h, l;
    h.a.x = __float2bfloat16(v.x); h.a.y = __float2bfloat16(v.y);
    h.b.x = __float2bfloat16(v.z); h.b.y = __float2bfloat16(v.w);
    l.a.x = __float2bfloat16(v.x - __bfloat162float(h.a.x));
    l.a.y = __float2bfloat16(v.y - __bfloat162float(h.a.y));
    l.b.x = __float2bfloat16(v.z - __bfloat162float(h.b.x));
    l.b.y = __float2bfloat16(v.w - __bfloat162float(h.b.y));
    *(bf16x4*)&hi[idx] = h;
    *(bf16x4*)&lo[idx] = l;
}
__device__ __forceinline__ void cvt4_store(bf16* dst, size_t idx, float4 v) {
    bf16x4 h;
    h.a.x = __float2bfloat16(v.x); h.a.y = __float2bfloat16(v.y);
    h.b.x = __float2bfloat16(v.z); h.b.y = __float2bfloat16(v.w);
    *(bf16x4*)&dst[idx] = h;
}
__device__ __forceinline__ void packsplit(float v0, float v1, uint32_t& hi, uint32_t& lo) {
    bf162 h, l;
    h.x = __float2bfloat16(v0); h.y = __float2bfloat16(v1);
    l.x = __float2bfloat16(v0 - __bfloat162float(h.x));
    l.y = __float2bfloat16(v1 - __bfloat162float(h.y));
    hi = *(uint32_t*)&h; lo = *(uint32_t*)&l;
}

__global__ void split4_kernel(const float* __restrict__ src, bf16* __restrict__ hi,
                              bf16* __restrict__ lo, int n) {
    int i = (blockIdx.x * 256 + threadIdx.x) * 4;
    if (i >= n) return;
    split4_store(hi, lo, i, *(const float4*)(src + i));
}

__global__ void cvt4_dual_kernel(const float* __restrict__ s1, bf16* __restrict__ d1,
                                 const float* __restrict__ s3, bf16* __restrict__ d3, int n) {
    int i = (blockIdx.x * 256 + threadIdx.x) * 4;
    if (i >= n) return;
    cvt4_store(d1, i, *(const float4*)(s1 + i));
    cvt4_store(d3, i, *(const float4*)(s3 + i));
}

__global__ void cvt4_kernel(const float* __restrict__ src, bf16* __restrict__ dst, int n) {
    int i = (blockIdx.x * 256 + threadIdx.x) * 4;
    if (i >= n) return;
    cvt4_store(dst, i, *(const float4*)(src + i));
}

__global__ void qkvpack_kernel(const float* __restrict__ wq, const float* __restrict__ wk,
                               const float* __restrict__ wv, bf16* __restrict__ hi,
                               bf16* __restrict__ lo) {
    int i = (blockIdx.x * 256 + threadIdx.x) * 4;
    if (i >= DIM * QKVN) return;
    int r = i / QKVN, c = i % QKVN;
    float4 v;
    if (c < 1024)      v = *(const float4*)(wq + (size_t)r * 1024 + c);
    else if (c < 1280) v = *(const float4*)(wk + (size_t)r * 256 + (c - 1024));
    else               v = *(const float4*)(wv + (size_t)r * 256 + (c - 1280));
    split4_store(hi, lo, i, v);
}

// ---------------- RMSNorm with split output ----------------
__global__ void rmsnorm_split_kernel(const float* __restrict__ x, const float* __restrict__ w,
                                     bf16* __restrict__ hi, bf16* __restrict__ lo) {
    int t = blockIdx.x;
    const float* xr = x + (size_t)t * DIM;
    float s = 0.f;
    for (int d = threadIdx.x; d < DIM; d += 256) { float v = xr[d]; s += v * v; }
    __shared__ float red[256];
    red[threadIdx.x] = s;
    __syncthreads();
    for (int o = 128; o > 0; o >>= 1) {
        if (threadIdx.x < o) red[threadIdx.x] += red[threadIdx.x + o];
        __syncthreads();
    }
    float inv = rsqrtf(red[0] / (float)DIM + 1e-6f);
    for (int d = threadIdx.x; d < DIM; d += 256) {
        float v = w[d] * xr[d] * inv;
        bf16 h = __float2bfloat16(v);
        size_t idx = (size_t)t * DIM + d;
        hi[idx] = h;
        lo[idx] = __float2bfloat16(v - __bfloat162float(h));
    }
}

// ---------------- bf16 split HMMA GEMM ----------------
// TERMS=3: fp32-ish (A hi+lo, B hi+lo), K-step 32, 3-stage ring.
// TERMS=1: pure bf16 (A hi, B hi), K-step 64, 3-stage ring (half the stage count).
template<int EPI, bool GATHER, bool EXPERT, bool ACAT, int TERMS>
__global__ void __launch_bounds__(256, 2) mma_gemm(
    const bf16* __restrict__ A1h, const bf16* __restrict__ A1l,
    const bf16* __restrict__ A2h, const bf16* __restrict__ A2l, int K1,
    const bf16* __restrict__ Bh_, const bf16* __restrict__ Bl_, size_t strideB,
    const float* __restrict__ bias, const float* __restrict__ aux,
    float* __restrict__ C, float* __restrict__ C2,
    bf16* __restrict__ Chi, bf16* __restrict__ Clo,
    int M, int N, int K)
{
    constexpr int KSTEP = (TERMS == 3) ? 32 : 64;
    constexpr int NKK   = KSTEP / 16;
    constexpr int ARS   = (TERMS == 3) ? ARS3 : ARS1;
    constexpr int APL   = (TERMS == 3) ? APL3 : APL1;
    constexpr int BPL   = (TERMS == 3) ? BPL3 : BPL1;
    constexpr int BOFF  = (TERMS == 3) ? 2 * APL3 : APL1;
    constexpr int STG   = (TERMS == 3) ? STAGE_G3 : STAGE_G1;

    const bf16* Bh = Bh_;
    const bf16* Bl = Bl_;
    if (EXPERT) {
        int e = g_tile_expert[blockIdx.y];
        if (e < 0) return;
        Bh += (size_t)e * strideB;
        if (TERMS == 3) Bl += (size_t)e * strideB;
    }
    extern __shared__ char dsm[];
    __shared__ int toks[128];
    uint32_t sbase = saddr(dsm);
    int tid = threadIdx.x;
    int m0 = blockIdx.y * 128, n0 = blockIdx.x * 128;

    if (GATHER) {
        if (tid < 128) toks[tid] = g_rows_token[m0 + tid];
        __syncthreads();
    }

    // load coordinates
    int ar = tid >> 1;
    int acn = (TERMS == 3) ? (tid & 1) * 16 : (tid & 1) * 32;
    int brr = (TERMS == 3) ? (tid >> 3) : (tid >> 2);
    int bcc = (TERMS == 3) ? (tid & 7) * 16 : (tid & 3) * 32;
    int arow = GATHER ? toks[ar] : (m0 + ar);
    int nst = K / KSTEP;

    auto load_stage = [&](int s, int buf) {
        int k0 = s * KSTEP;
        const bf16 *pah = A1h, *pal = A1l;
        int lda = K, kl = k0;
        if (ACAT) {
            if (k0 >= K1) { pah = A2h; pal = A2l; lda = K - K1; kl = k0 - K1; }
            else          { lda = K1; }
        }
        const bf16* gah = pah + (size_t)arow * lda + kl + acn;
        uint32_t ab = sbase + buf * STG + (ar * ARS + acn) * 2;
        if (TERMS == 3) {
            cp16(ab, gah);           cp16(ab + 16, gah + 8);
            const bf16* gal = pal + (size_t)arow * lda + kl + acn;
            cp16(ab + APL, gal);     cp16(ab + APL + 16, gal + 8);
        } else {
            #pragma unroll
            for (int c = 0; c < 4; ++c) cp16(ab + c * 16, gah + c * 8);
        }
        const bf16* gbh = Bh + (size_t)(k0 + brr) * N + n0 + bcc;
        uint32_t bb = sbase + buf * STG + BOFF + (brr * 136 + bcc) * 2;
        if (TERMS == 3) {
            cp16(bb, gbh);           cp16(bb + 16, gbh + 8);
            const bf16* gbl = Bl + (size_t)(k0 + brr) * N + n0 + bcc;
            cp16(bb + BPL, gbl);     cp16(bb + BPL + 16, gbl + 8);
        } else {
            #pragma unroll
            for (int c = 0; c < 4; ++c) cp16(bb + c * 16, gbh + c * 8);
        }
        cp_commit();
    };

    float acc[2][8][4];
    #pragma unroll
    for (int i = 0; i < 2; ++i)
        #pragma unroll
        for (int j = 0; j < 8; ++j)
            #pragma unroll
            for (int q = 0; q < 4; ++q) acc[i][j][q] = 0.f;

    int lane = tid & 31;
    int warp = tid >> 5;
    int wm = (warp >> 1) * 32, wn = (warp & 1) * 64;
    int a_row = lane & 15, a_col = (lane >> 4) * 8;
    int b_krow = (lane & 7) + ((lane >> 3) & 1) * 8;
    int b_nadd = (lane >> 4) * 8;

    load_stage(0, 0);
    if (nst > 1) load_stage(1, 1);

    for (int s = 0; s < nst; ++s) {
        int buf = s % 3;
        int rem = nst - 1 - s;
        if (rem >= 1) cp_wait<1>(); else cp_wait<0>();
        __syncthreads();
        if (s + 2 < nst) load_stage(s + 2, (s + 2) % 3);

        uint32_t abuf = sbase + buf * STG;
        uint32_t bbuf = abuf + BOFF;
        #pragma unroll
        for (int kk = 0; kk < NKK; ++kk) {
            uint32_t Ah[2][4], Al[2][4];
            #pragma unroll
            for (int mt = 0; mt < 2; ++mt) {
                uint32_t aoff = ((wm + mt * 16 + a_row) * ARS + kk * 16 + a_col) * 2;
                ldsm4(abuf + aoff, Ah[mt]);
                if (TERMS == 3) ldsm4(abuf + APL + aoff, Al[mt]);
            }
            #pragma unroll
            for (int half = 0; half < 2; ++half) {
                uint32_t Bhf[4][2], Blf[4][2];
                #pragma unroll
                for (int g16 = 0; g16 < 2; ++g16) {
                    uint32_t boff = ((kk * 16 + b_krow) * 136 + wn + half * 32 + g16 * 16 + b_nadd) * 2;
                    uint32_t r0, r1, r2, r3;
                    ldsm4t(bbuf + boff, r0, r1, r2, r3);
                    Bhf[2 * g16][0] = r0; Bhf[2 * g16][1] = r1;
                    Bhf[2 * g16 + 1][0] = r2; Bhf[2 * g16 + 1][1] = r3;
                    if (TERMS == 3) {
                        ldsm4t(bbuf + BPL + boff, r0, r1, r2, r3);
                        Blf[2 * g16][0] = r0; Blf[2 * g16][1] = r1;
                        Blf[2 * g16 + 1][0] = r2; Blf[2 * g16 + 1][1] = r3;
                    }
                }
                #pragma unroll
                for (int mt = 0; mt < 2; ++mt)
                    #pragma unroll
                    for (int nn = 0; nn < 4; ++nn)
                        mma_bf16(acc[mt][half * 4 + nn], Ah[mt], Bhf[nn]);
                if (TERMS == 3) {
                    #pragma unroll
                    for (int mt = 0; mt < 2; ++mt)
                        #pragma unroll
                        for (int nn = 0; nn < 4; ++nn)
                            mma_bf16(acc[mt][half * 4 + nn], Ah[mt], Blf[nn]);
                    #pragma unroll
                    for (int mt = 0; mt < 2; ++mt)
                        #pragma unroll
                        for (int nn = 0; nn < 4; ++nn)
                            mma_bf16(acc[mt][half * 4 + nn], Al[mt], Bhf[nn]);
                }
            }
        }
    }

    int g = lane >> 2, ti2 = (lane & 3) * 2;
    #pragma unroll
    for (int mt = 0; mt < 2; ++mt) {
        #pragma unroll
        for (int nn = 0; nn < 8; ++nn) {
            int col = n0 + wn + nn * 8 + ti2;
            #pragma unroll
            for (int hf = 0; hf < 2; ++hf) {
                int row = m0 + wm + mt * 16 + g + hf * 8;
                float v0 = acc[mt][nn][2 * hf], v1 = acc[mt][nn][2 * hf + 1];
                size_t idx = (size_t)row * N + col;
                if (EPI == 0) {
                    if (bias) { v0 += bias[col]; v1 += bias[col + 1]; }
                    *(float2*)&C[idx] = make_float2(v0, v1);
                } else if (EPI == 1) {
                    split_store(Chi, Clo, idx, v0, v1);
                } else if (EPI == 2) {
                    v0 += bias[col]; v1 += bias[col + 1];
                    *(float2*)&C[idx] = make_float2(v0, v1);
                    float2 r = *(const float2*)&aux[idx];
                    *(float2*)&C2[idx] = make_float2(v0 + r.x, v1 + r.y);
                } else { // EPI 3: silu(aux)*acc -> bf16 hi (Clo optional)
                    float2 hv = *(const float2*)&aux[idx];
                    float s0 = hv.x / (1.f + __expf(-hv.x));
                    float s1 = hv.y / (1.f + __expf(-hv.y));
                    float r0 = v0 * s0, r1 = v1 * s1;
                    if (Clo) {
                        split_store(Chi, Clo, idx, r0, r1);
                    } else {
                        bf162 h2;
                        h2.x = __float2bfloat16(r0);
                        h2.y = __float2bfloat16(r1);
                        *(bf162*)&Chi[idx] = h2;
                    }
                }
            }
        }
    }
}

// ---------------- tensor-core attention, Q in smem, 2 CTAs/SM ----------------
__global__ void __launch_bounds__(256, 2) attn_mma(
    const bf16* __restrict__ Qh, const bf16* __restrict__ Ql,
    bf16* __restrict__ Ohi, bf16* __restrict__ Olo)
{
    extern __shared__ char dsm[];
    uint32_t sb = saddr(dsm);
    uint32_t kvbase = sb + ATQ_SZ;
    int b = blockIdx.z, h = blockIdx.y, q0 = blockIdx.x * 128;
    int kvh = h >> 2;
    int tid = threadIdx.x, lane = tid & 31, w = tid >> 5;

    {
        int plane = tid >> 7, row = tid & 127;
        const bf16* src = (plane ? Ql : Qh) + (size_t)(b * SEQ + q0 + row) * QKVN + h * HD;
        uint32_t dst = sb + plane * ATQ_PL + row * 144;
        #pragma unroll
        for (int c = 0; c < 8; ++c) cp16(dst + c * 16, src + c * 8);
        cp_commit();
    }

    auto loadkv = [&](int kt, int buf) {
        int p = tid >> 6, row = tid & 63;
        size_t goff = (size_t)(b * SEQ + kt * 64 + row) * QKVN + DIM + kvh * HD;
        if (p >= 2) goff += NKVH * HD;
        const bf16* src = ((p & 1) ? Ql : Qh) + goff;
        uint32_t dst = kvbase + buf * AT_BUF + p * AT_PL + row * 144;
        #pragma unroll
        for (int c = 0; c < 8; ++c) cp16(dst + c * 16, src + c * 8);
        cp_commit();
    };

    float O[8][4];
    #pragma unroll
    for (int i = 0; i < 8; ++i)
        #pragma unroll
        for (int q = 0; q < 4; ++q) O[i][q] = 0.f;
    float l0 = 0.f, l1 = 0.f;

    int qa_r = lane & 15, qa_c = (lane >> 4) * 8;
    int kb_r = (lane & 7) + ((lane >> 4) & 1) * 8;
    int kb_c = ((lane >> 3) & 1) * 8;
    int vb_r = (lane & 7) + ((lane >> 3) & 1) * 8;
    int vb_c = (lane >> 4) * 8;

    loadkv(0, 0);
    loadkv(1, 1);

    for (int kt = 0; kt < SEQ / 64; ++kt) {
        int buf = kt & 1;
        if (kt + 1 < SEQ / 64) cp_wait<1>(); else cp_wait<0>();
        __syncthreads();
        uint32_t kb = kvbase + buf * AT_BUF;
        uint32_t vb = kb + 2 * AT_PL;

        float s[8][4];
        #pragma unroll
        for (int i = 0; i < 8; ++i)
            #pragma unroll
            for (int q = 0; q < 4; ++q) s[i][q] = 0.f;
        #pragma unroll
        for (int kk = 0; kk < 4; ++kk) {
            uint32_t qh[4], ql[4];
            uint32_t qoff = (uint32_t)((w * 16 + qa_r) * 144 + (kk * 16 + qa_c) * 2);
            ldsm4(sb + qoff, qh);
            ldsm4(sb + ATQ_PL + qoff, ql);
            uint32_t bh[8][2], bl[8][2];
            #pragma unroll
            for (int g2 = 0; g2 < 4; ++g2) {
                uint32_t tmp[4];
                uint32_t off = (uint32_t)((g2 * 16 + kb_r) * 144 + (kk * 16 + kb_c) * 2);
                ldsm4(kb + off, tmp);
                bh[2 * g2][0] = tmp[0]; bh[2 * g2][1] = tmp[1];
                bh[2 * g2 + 1][0] = tmp[2]; bh[2 * g2 + 1][1] = tmp[3];
                ldsm4(kb + AT_PL + off, tmp);
                bl[2 * g2][0] = tmp[0]; bl[2 * g2][1] = tmp[1];
                bl[2 * g2 + 1][0] = tmp[2]; bl[2 * g2 + 1][1] = tmp[3];
            }
            #pragma unroll
            for (int nn = 0; nn < 8; ++nn) mma_bf16(s[nn], qh, bh[nn]);
            #pragma unroll
            for (int nn = 0; nn < 8; ++nn) mma_bf16(s[nn], qh, bl[nn]);
            #pragma unroll
            for (int nn = 0; nn < 8; ++nn) mma_bf16(s[nn], ql, bh[nn]);
        }

        #pragma unroll
        for (int nn = 0; nn < 8; ++nn) {
            #pragma unroll
            for (int q = 0; q < 4; ++q) s[nn][q] = __expf(s[nn][q] * 0.125f);
            l0 += s[nn][0] + s[nn][1];
            l1 += s[nn][2] + s[nn][3];
        }
        uint32_t pah[4][4], pal[4][4];
        #pragma unroll
        for (int kk = 0; kk < 4; ++kk) {
            packsplit(s[2 * kk][0],     s[2 * kk][1],     pah[kk][0], pal[kk][0]);
            packsplit(s[2 * kk][2],     s[2 * kk][3],     pah[kk][1], pal[kk][1]);
            packsplit(s[2 * kk + 1][0], s[2 * kk + 1][1], pah[kk][2], pal[kk][2]);
            packsplit(s[2 * kk + 1][2], s[2 * kk + 1][3], pah[kk][3], pal[kk][3]);
        }

        #pragma unroll
        for (int kk = 0; kk < 4; ++kk) {
            uint32_t vh[8][2], vl[8][2];
            #pragma unroll
            for (int g2 = 0; g2 < 4; ++g2) {
                uint32_t r0, r1, r2, r3;
                uint32_t off = (uint32_t)((kk * 16 + vb_r) * 144 + (g2 * 16 + vb_c) * 2);
                ldsm4t(vb + off, r0, r1, r2, r3);
                vh[2 * g2][0] = r0; vh[2 * g2][1] = r1;
                vh[2 * g2 + 1][0] = r2; vh[2 * g2 + 1][1] = r3;
                ldsm4t(vb + AT_PL + off, r0, r1, r2, r3);
                vl[2 * g2][0] = r0; vl[2 * g2][1] = r1;
                vl[2 * g2 + 1][0] = r2; vl[2 * g2 + 1][1] = r3;
            }
            #pragma unroll
            for (int nn = 0; nn < 8; ++nn) mma_bf16(O[nn], pah[kk], vh[nn]);
            #pragma unroll
            for (int nn = 0; nn < 8; ++nn) mma_bf16(O[nn], pah[kk], vl[nn]);
            #pragma unroll
            for (int nn = 0; nn < 8; ++nn) mma_bf16(O[nn], pal[kk], vh[nn]);
        }
        __syncthreads();
        if (kt + 2 < SEQ / 64) loadkv(kt + 2, buf);
    }

    l0 += __shfl_xor_sync(0xffffffffu, l0, 1);
    l0 += __shfl_xor_sync(0xffffffffu, l0, 2);
    l1 += __shfl_xor_sync(0xffffffffu, l1, 1);
    l1 += __shfl_xor_sync(0xffffffffu, l1, 2);
    float inv0 = 1.f / l0, inv1 = 1.f / l1;

    int g = lane >> 2, t2 = (lane & 3) * 2;
    int row0 = b * SEQ + q0 + w * 16 + g;
    #pragma unroll
    for (int nn = 0; nn < 8; ++nn) {
        int col = h * HD + nn * 8 + t2;
        split_store(Ohi, Olo, (size_t)row0 * DIM + col, O[nn][0] * inv0, O[nn][1] * inv0);
        split_store(Ohi, Olo, (size_t)(row0 + 8) * DIM + col, O[nn][2] * inv1, O[nn][3] * inv1);
    }
}

// ---------------- MoE routing ----------------
__global__ void route_init_kernel() {
    int i = blockIdx.x * 256 + threadIdx.x;
    if (i < MAXR) g_rows_token[i] = 0;
    if (i < NE) { g_cnt[i] = 0; g_fill[i] = 0; }
}

__global__ void gate_kernel(const bf16* __restrict__ hh, const bf16* __restrict__ hl,
                            const float* __restrict__ gw) {
    int t = blockIdx.x;
    int lane = threadIdx.x;
    float p[NE];
    #pragma unroll
    for (int e = 0; e < NE; ++e) p[e] = 0.f;
    size_t base = (size_t)t * DIM;
    for (int d = lane; d < DIM; d += 32) {
        float x = __bfloat162float(hh[base + d]) + __bfloat162float(hl[base + d]);
        const float* g = gw + (size_t)d * NE;
        #pragma unroll
        for (int e = 0; e < NE; ++e) p[e] += x * g[e];
    }
    #pragma unroll
    for (int o = 16; o; o >>= 1) {
        #pragma unroll
        for (int e = 0; e < NE; ++e) p[e] += __shfl_xor_sync(0xffffffffu, p[e], o);
    }
    if (lane == 0) {
        int i0 = 0; float l0 = p[0];
        for (int e = 1; e < NE; ++e) if (p[e] > l0) { l0 = p[e]; i0 = e; }
        int i1 = -1; float l1 = -1e30f;
        for (int e = 0; e < NE; ++e) if (e != i0 && p[e] > l1) { l1 = p[e]; i1 = e; }
        float w0 = 1.f / (1.f + __expf(l1 - l0));
        float w1 = 1.f - w0;
        g_expsel[2 * t] = i0; g_expsel[2 * t + 1] = i1;
        g_expw[2 * t] = w0;  g_expw[2 * t + 1] = w1;
        atomicAdd(&g_cnt[i0], 1);
        atomicAdd(&g_cnt[i1], 1);
    }
}

__global__ void scan_kernel() {
    int off = 0;
    for (int e = 0; e < NE; ++e) {
        g_pstart[e] = off;
        int pad = (g_cnt[e] + 127) & ~127;
        int t0 = off >> 7;
        off += pad;
        int t1 = off >> 7;
        for (int t = t0; t < t1; ++t) g_tile_expert[t] = e;
    }
    for (int t = off >> 7; t < MAXTILES; ++t) g_tile_expert[t] = -1;
}

__global__ void scatter_kernel() {
    int t = blockIdx.x * 256 + threadIdx.x;
    if (t >= T_TOK) return;
    #pragma unroll
    for (int slot = 0; slot < 2; ++slot) {
        int e = g_expsel[2 * t + slot];
        int pos = g_pstart[e] + atomicAdd(&g_fill[e], 1);
        g_rows_token[pos] = t;
        g_tok_rowpos[2 * t + slot] = pos;
    }
}

// ---------------- combine ----------------
__global__ void combine_kernel(const float* __restrict__ h1, float* __restrict__ out,
                               bf16* __restrict__ ohi, bf16* __restrict__ olo) {
    int t = blockIdx.x;
    int r0 = g_tok_rowpos[2 * t], r1 = g_tok_rowpos[2 * t + 1];
    float w0 = g_expw[2 * t], w1 = g_expw[2 * t + 1];
    const float* a  = h1 + (size_t)t * DIM;
    const float* p0 = g_moe + (size_t)r0 * DIM;
    const float* p1 = g_moe + (size_t)r1 * DIM;
    size_t base = (size_t)t * DIM;
    for (int d = threadIdx.x * 4; d < DIM; d += 256 * 4) {
        float4 va = *(const float4*)&a[d];
        float4 v0 = *(const float4*)&p0[d];
        float4 v1 = *(const float4*)&p1[d];
        float4 v;
        v.x = va.x + w0 * v0.x + w1 * v1.x;
        v.y = va.y + w0 * v0.y + w1 * v1.y;
        v.z = va.z + w0 * v0.z + w1 * v1.z;
        v.w = va.w + w0 * v0.w + w1 * v1.w;
        *(float4*)&out[base + d] = v;
        split4_store(ohi, olo, base + d, v);
    }
}

// ---------------- launch ----------------
static inline int cdiv(int a, int b) { return (a + b - 1) / b; }

extern "C" void kernel_launch(void* const* d_in, const int* in_sizes, int n_in,
                              void* d_out, int out_size) {
    const float* hidden = (const float*)d_in[0];
    const float* prev   = (const float*)d_in[2];
    const float* wq     = (const float*)d_in[3];
    const float* wk     = (const float*)d_in[4];
    const float* wv     = (const float*)d_in[5];
    const float* wo     = (const float*)d_in[6];
    const float* mix_w  = (const float*)d_in[7];
    const float* mix_b  = (const float*)d_in[8];
    const float* gate_w = (const float*)d_in[9];
    const float* w1     = (const float*)d_in[10];
    const float* w2     = (const float*)d_in[11];
    const float* w3     = (const float*)d_in[12];
    const float* ln1    = (const float*)d_in[13];
    const float* ln2    = (const float*)d_in[14];
    const float* comp_w = (const float*)d_in[15];
    const float* comp_b = (const float*)d_in[16];

    float* out_h     = (float*)d_out;
    float* out_mixed = out_h + (size_t)T_TOK * DIM;
    float* out_comp  = out_mixed + (size_t)T_TOK * DIM;

    float *h1, *h1buf, *moe;
    cudaGetSymbolAddress((void**)&h1, g_h1);
    cudaGetSymbolAddress((void**)&h1buf, g_h1buf);
    cudaGetSymbolAddress((void**)&moe, g_moe);
    bf16 *qxh,*qxl,*xnh,*xnl,*atth,*attl,*prevh,*prevl,*h2h,*h2l,*acth,*outhh,*outhl;
    cudaGetSymbolAddress((void**)&qxh, g_qxh);   cudaGetSymbolAddress((void**)&qxl, g_qxl);
    cudaGetSymbolAddress((void**)&xnh, g_xnh);   cudaGetSymbolAddress((void**)&xnl, g_xnl);
    cudaGetSymbolAddress((void**)&atth, g_atth); cudaGetSymbolAddress((void**)&attl, g_attl);
    cudaGetSymbolAddress((void**)&prevh, g_prevh); cudaGetSymbolAddress((void**)&prevl, g_prevl);
    cudaGetSymbolAddress((void**)&h2h, g_h2h);   cudaGetSymbolAddress((void**)&h2l, g_h2l);
    cudaGetSymbolAddress((void**)&acth, g_acth);
    cudaGetSymbolAddress((void**)&outhh, g_outhh); cudaGetSymbolAddress((void**)&outhl, g_outhl);
    bf16 *wqkvh,*wqkvl,*woh,*wol,*mth,*mtl,*meh,*mel,*w1h,*w2h,*w3h,*cwh,*cwl;
    cudaGetSymbolAddress((void**)&wqkvh, g_wqkvh); cudaGetSymbolAddress((void**)&wqkvl, g_wqkvl);
    cudaGetSymbolAddress((void**)&woh, g_woh);     cudaGetSymbolAddress((void**)&wol, g_wol);
    cudaGetSymbolAddress((void**)&mth, g_mixtoph); cudaGetSymbolAddress((void**)&mtl, g_mixtopl);
    cudaGetSymbolAddress((void**)&meh, g_mixeffh); cudaGetSymbolAddress((void**)&mel, g_mixeffl);
    cudaGetSymbolAddress((void**)&w1h, g_w1h);
    cudaGetSymbolAddress((void**)&w2h, g_w2h);
    cudaGetSymbolAddress((void**)&w3h, g_w3h);
    cudaGetSymbolAddress((void**)&cwh, g_cwh);     cudaGetSymbolAddress((void**)&cwl, g_cwl);

    cudaFuncSetAttribute(mma_gemm<1,false,false,false,3>, cudaFuncAttributeMaxDynamicSharedMemorySize, SMEM_G3);
    cudaFuncSetAttribute(mma_gemm<2,false,false,true,3>,  cudaFuncAttributeMaxDynamicSharedMemorySize, SMEM_G3);
    cudaFuncSetAttribute(mma_gemm<0,true,true,false,1>,   cudaFuncAttributeMaxDynamicSharedMemorySize, SMEM_G1);
    cudaFuncSetAttribute(mma_gemm<3,true,true,false,1>,   cudaFuncAttributeMaxDynamicSharedMemorySize, SMEM_G1);
    cudaFuncSetAttribute(mma_gemm<0,false,true,false,1>,  cudaFuncAttributeMaxDynamicSharedMemorySize, SMEM_G1);
    cudaFuncSetAttribute(mma_gemm<0,false,false,false,3>, cudaFuncAttributeMaxDynamicSharedMemorySize, SMEM_G3);
    cudaFuncSetAttribute(attn_mma, cudaFuncAttributeMaxDynamicSharedMemorySize, SMEM_AT);

    qkvpack_kernel<<<cdiv(DIM * QKVN / 4, 256), 256>>>(wq, wk, wv, wqkvh, wqkvl);
    rmsnorm_split_kernel<<<T_TOK, 256>>>(hidden, ln1, xnh, xnl);

    mma_gemm<1,false,false,false,3><<<dim3(QKVN / 128, T_TOK / 128), 256, SMEM_G3>>>(
        xnh, xnl, nullptr, nullptr, 0, wqkvh, wqkvl, 0,
        nullptr, nullptr, nullptr, nullptr, qxh, qxl, T_TOK, QKVN, DIM);

    attn_mma<<<dim3(SEQ / 128, NH, NB), 256, SMEM_AT>>>(qxh, qxl, atth, attl);

    // effective mixer weight: mixeff = [wo @ mix_top ; mix_bot]
    split4_kernel<<<cdiv(DIM * DIM / 4, 256), 256>>>(wo, woh, wol, DIM * DIM);
    split4_kernel<<<cdiv(DIM * DIM / 4, 256), 256>>>(mix_w, mth, mtl, DIM * DIM);
    mma_gemm<1,false,false,false,3><<<dim3(DIM / 128, DIM / 128), 256, SMEM_G3>>>(
        woh, wol, nullptr, nullptr, 0, mth, mtl, 0,
        nullptr, nullptr, nullptr, nullptr, meh, mel, DIM, DIM, DIM);
    split4_kernel<<<cdiv(DIM * DIM / 4, 256), 256>>>(mix_w + (size_t)DIM * DIM,
                                                     meh + (size_t)DIM * DIM,
                                                     mel + (size_t)DIM * DIM, DIM * DIM);
    split4_kernel<<<cdiv(T_TOK * DIM / 4, 256), 256>>>(prev, prevh, prevl, T_TOK * DIM);

    mma_gemm<2,false,false,true,3><<<dim3(DIM / 128, T_TOK / 128), 256, SMEM_G3>>>(
        atth, attl, prevh, prevl, DIM, meh, mel, 0,
        mix_b, hidden, out_mixed, h1, nullptr, nullptr, T_TOK, DIM, 2 * DIM);

    rmsnorm_split_kernel<<<T_TOK, 256>>>(h1, ln2, h2h, h2l);

    route_init_kernel<<<cdiv(MAXR, 256), 256>>>();
    gate_kernel<<<T_TOK, 32>>>(h2h, h2l, gate_w);
    scan_kernel<<<1, 1>>>();
    scatter_kernel<<<T_TOK / 256, 256>>>();

    cvt4_dual_kernel<<<cdiv(NE * DIM * FF / 4, 256), 256>>>(w1, w1h, w3, w3h, NE * DIM * FF);

    // MoE pure-bf16 (TERMS=1, K-step 64)
    mma_gemm<0,true,true,false,1><<<dim3(FF / 128, MAXTILES), 256, SMEM_G1>>>(
        h2h, nullptr, nullptr, nullptr, 0, w1h, nullptr, (size_t)DIM * FF,
        nullptr, nullptr, h1buf, nullptr, nullptr, nullptr, MAXR, FF, DIM);

    mma_gemm<3,true,true,false,1><<<dim3(FF / 128, MAXTILES), 256, SMEM_G1>>>(
        h2h, nullptr, nullptr, nullptr, 0, w3h, nullptr, (size_t)DIM * FF,
        nullptr, h1buf, nullptr, nullptr, acth, nullptr, MAXR, FF, DIM);

    cvt4_kernel<<<cdiv(NE * FF * DIM / 4, 256), 256>>>(w2, w2h, NE * FF * DIM);

    mma_gemm<0,false,true,false,1><<<dim3(DIM / 128, MAXTILES), 256, SMEM_G1>>>(
        acth, nullptr, nullptr, nullptr, 0, w2h, nullptr, (size_t)FF * DIM,
        nullptr, nullptr, moe, nullptr, nullptr, nullptr, MAXR, DIM, FF);

    combine_kernel<<<T_TOK, 256>>>(h1, out_h, outhh, outhl);

    split4_kernel<<<cdiv(DIM * NCOMP / 4, 256), 256>>>(comp_w, cwh, cwl, DIM * NCOMP);

    mma_gemm<0,false,false,false,3><<<dim3(NCOMP / 128, T_TOK / 128), 256, SMEM_G3>>>(
        outhh, outhl, nullptr, nullptr, 0, cwh, cwl, 0,
        comp_b, nullptr, out_comp, nullptr, nullptr, nullptr, T_TOK, NCOMP, DIM);
}

// round 16
// speedup vs baseline: 1.1145x; 1.1145x over previous
#include <cuda_runtime.h>
#include <cuda_bf16.h>
#include <math.h>
#include <stdint.h>

// ---------------- problem constants ----------------
#define T_TOK 4096
#define DIM   1024
#define SEQ   1024
#define NB    4
#define NH    16
#define NKVH  4
#define HD    64
#define NE    8
#define FF    2816
#define NCOMP 256
#define QKVN  1536
#define MAXR  9216
#define MAXTILES 72

typedef __nv_bfloat16 bf16;
typedef __nv_bfloat162 bf162;
typedef unsigned long long u64;

struct bf16x4 { bf162 a, b; };

// ---------------- scratch (device globals) ----------------
__device__ float g_h1[(size_t)T_TOK * DIM];
__device__ float g_moe[(size_t)MAXR * DIM];

__device__ bf16 g_h1bufb[(size_t)MAXR * FF];     // bf16 MoE intermediate
__device__ bf16 g_qxh[(size_t)T_TOK * QKVN], g_qxl[(size_t)T_TOK * QKVN];
__device__ bf16 g_xnh[(size_t)T_TOK * DIM],  g_xnl[(size_t)T_TOK * DIM];
__device__ bf16 g_atth[(size_t)T_TOK * DIM], g_attl[(size_t)T_TOK * DIM];
__device__ bf16 g_prevh[(size_t)T_TOK * DIM],g_prevl[(size_t)T_TOK * DIM];
__device__ bf16 g_h2h[(size_t)T_TOK * DIM],  g_h2l[(size_t)T_TOK * DIM];
__device__ bf16 g_acth[(size_t)MAXR * FF];
__device__ bf16 g_outhh[(size_t)T_TOK * DIM],g_outhl[(size_t)T_TOK * DIM];

// weights [K][N] layout
__device__ bf16 g_wqkvh[(size_t)DIM * QKVN], g_wqkvl[(size_t)DIM * QKVN];
__device__ bf16 g_woh[(size_t)DIM * DIM],    g_wol[(size_t)DIM * DIM];
__device__ bf16 g_mixtoph[(size_t)DIM * DIM], g_mixtopl[(size_t)DIM * DIM];
__device__ bf16 g_mixeffh[(size_t)2 * DIM * DIM], g_mixeffl[(size_t)2 * DIM * DIM];
__device__ bf16 g_w1h[(size_t)NE * DIM * FF];       // hi-only (bf16 MoE)
__device__ bf16 g_w2h[(size_t)NE * FF * DIM];
__device__ bf16 g_w3h[(size_t)NE * DIM * FF];
__device__ bf16 g_cwh[(size_t)DIM * NCOMP],  g_cwl[(size_t)DIM * NCOMP];

__device__ int   g_expsel[T_TOK * 2];
__device__ float g_expw[T_TOK * 2];
__device__ int   g_cnt[NE];
__device__ int   g_fill[NE];
__device__ int   g_pstart[NE];
__device__ int   g_rows_token[MAXR];
__device__ int   g_tok_rowpos[T_TOK * 2];
__device__ int   g_tile_expert[MAXTILES];

// ---------------- asm helpers ----------------
__device__ __forceinline__ uint32_t saddr(const void* p) {
    return (uint32_t)__cvta_generic_to_shared(p);
}
__device__ __forceinline__ void cp16(uint32_t s, const void* g) {
    asm volatile("cp.async.cg.shared.global [%0], [%1], 16;\n" :: "r"(s), "l"(g));
}
__device__ __forceinline__ void cp_commit() { asm volatile("cp.async.commit_group;\n"); }
template<int N> __device__ __forceinline__ void cp_wait() {
    asm volatile("cp.async.wait_group %0;\n" :: "n"(N));
}
__device__ __forceinline__ void ldsm4(uint32_t a, uint32_t* r) {
    asm volatile("ldmatrix.sync.aligned.m8n8.x4.shared.b16 {%0,%1,%2,%3}, [%4];\n"
                 : "=r"(r[0]), "=r"(r[1]), "=r"(r[2]), "=r"(r[3]) : "r"(a));
}
__device__ __forceinline__ void ldsm4t(uint32_t a, uint32_t& r0, uint32_t& r1, uint32_t& r2, uint32_t& r3) {
    asm volatile("ldmatrix.sync.aligned.m8n8.x4.trans.shared.b16 {%0,%1,%2,%3}, [%4];\n"
                 : "=r"(r0), "=r"(r1), "=r"(r2), "=r"(r3) : "r"(a));
}
__device__ __forceinline__ void mma_bf16(float c[4], const uint32_t a[4], const uint32_t b[2]) {
    asm volatile("mma.sync.aligned.m16n8k16.row.col.f32.bf16.bf16.f32 "
                 "{%0,%1,%2,%3}, {%4,%5,%6,%7}, {%8,%9}, {%0,%1,%2,%3};\n"
                 : "+f"(c[0]), "+f"(c[1]), "+f"(c[2]), "+f"(c[3])
                 : "r"(a[0]), "r"(a[1]), "r"(a[2]), "r"(a[3]), "r"(b[0]), "r"(b[1]));
}

// ---------------- smem geometry (GEMM) ----------------
#define APL (128 * 40 * 2)          // A hi plane
#define ASZ (2 * APL)
#define BPL (32 * 136 * 2)
#define BSZ (2 * BPL)
#define STAGE_G3 (ASZ + BSZ)        // 37888  (TERMS=3, 3 stages)
#define SMEM_G3  (3 * STAGE_G3)
#define STAGE_G1 (APL + BPL)        // 18944  (TERMS=1, 5 stages)
#define SMEM_G1  (5 * STAGE_G1)     // 94720 -> 2 CTAs/SM

// attention smem
#define ATQ_PL  18432
#define ATQ_SZ  (2 * ATQ_PL)
#define AT_PL   9216
#define AT_BUF  (4 * AT_PL)
#define SMEM_AT (ATQ_SZ + 2 * AT_BUF)  // 110592 -> 2 CTAs/SM

// ---------------- split helpers ----------------
__device__ __forceinline__ void split_store(bf16* hi, bf16* lo, size_t idx, float v0, float v1) {
    bf162 h2, l2;
    h2.x = __float2bfloat16(v0); h2.y = __float2bfloat16(v1);
    l2.x = __float2bfloat16(v0 - __bfloat162float(h2.x));
    l2.y = __float2bfloat16(v1 - __bfloat162float(h2.y));
    *(bf162*)&hi[idx] = h2;
    *(bf162*)&lo[idx] = l2;
}
__device__ __forceinline__ void split4_store(bf16* hi, bf16* lo, size_t idx, float4 v) {
    bf16x4 h, l;
    h.a.x = __float2bfloat16(v.x); h.a.y = __float2bfloat16(v.y);
    h.b.x = __float2bfloat16(v.z); h.b.y = __float2bfloat16(v.w);
    l.a.x = __float2bfloat16(v.x - __bfloat162float(h.a.x));
    l.a.y = __float2bfloat16(v.y - __bfloat162float(h.a.y));
    l.b.x = __float2bfloat16(v.z - __bfloat162float(h.b.x));
    l.b.y = __float2bfloat16(v.w - __bfloat162float(h.b.y));
    *(bf16x4*)&hi[idx] = h;
    *(bf16x4*)&lo[idx] = l;
}
__device__ __forceinline__ void cvt4_store(bf16* dst, size_t idx, float4 v) {
    bf16x4 h;
    h.a.x = __float2bfloat16(v.x); h.a.y = __float2bfloat16(v.y);
    h.b.x = __float2bfloat16(v.z); h.b.y = __float2bfloat16(v.w);
    *(bf16x4*)&dst[idx] = h;
}
__device__ __forceinline__ void packsplit(float v0, float v1, uint32_t& hi, uint32_t& lo) {
    bf162 h, l;
    h.x = __float2bfloat16(v0); h.y = __float2bfloat16(v1);
    l.x = __float2bfloat16(v0 - __bfloat162float(h.x));
    l.y = __float2bfloat16(v1 - __bfloat162float(h.y));
    hi = *(uint32_t*)&h; lo = *(uint32_t*)&l;
}

__global__ void split4_kernel(const float* __restrict__ src, bf16* __restrict__ hi,
                              bf16* __restrict__ lo, int n) {
    int i = (blockIdx.x * 256 + threadIdx.x) * 4;
    if (i >= n) return;
    split4_store(hi, lo, i, *(const float4*)(src + i));
}

// dual fp32->hi/lo split (two independent matrices of same size)
__global__ void split4_dual_kernel(const float* __restrict__ s1, bf16* __restrict__ h1,
                                   bf16* __restrict__ l1, const float* __restrict__ s3,
                                   bf16* __restrict__ h3, bf16* __restrict__ l3, int n) {
    int i = (blockIdx.x * 256 + threadIdx.x) * 4;
    if (i >= n) return;
    split4_store(h1, l1, i, *(const float4*)(s1 + i));
    split4_store(h3, l3, i, *(const float4*)(s3 + i));
}

__global__ void cvt4_dual_kernel(const float* __restrict__ s1, bf16* __restrict__ d1,
                                 const float* __restrict__ s3, bf16* __restrict__ d3, int n) {
    int i = (blockIdx.x * 256 + threadIdx.x) * 4;
    if (i >= n) return;
    cvt4_store(d1, i, *(const float4*)(s1 + i));
    cvt4_store(d3, i, *(const float4*)(s3 + i));
}

__global__ void cvt4_kernel(const float* __restrict__ src, bf16* __restrict__ dst, int n) {
    int i = (blockIdx.x * 256 + threadIdx.x) * 4;
    if (i >= n) return;
    cvt4_store(dst, i, *(const float4*)(src + i));
}

__global__ void qkvpack_kernel(const float* __restrict__ wq, const float* __restrict__ wk,
                               const float* __restrict__ wv, bf16* __restrict__ hi,
                               bf16* __restrict__ lo) {
    int i = (blockIdx.x * 256 + threadIdx.x) * 4;
    if (i >= DIM * QKVN) return;
    int r = i / QKVN, c = i % QKVN;
    float4 v;
    if (c < 1024)      v = *(const float4*)(wq + (size_t)r * 1024 + c);
    else if (c < 1280) v = *(const float4*)(wk + (size_t)r * 256 + (c - 1024));
    else               v = *(const float4*)(wv + (size_t)r * 256 + (c - 1280));
    split4_store(hi, lo, i, v);
}

// ---------------- RMSNorm with split output ----------------
__global__ void rmsnorm_split_kernel(const float* __restrict__ x, const float* __restrict__ w,
                                     bf16* __restrict__ hi, bf16* __restrict__ lo) {
    int t = blockIdx.x;
    const float* xr = x + (size_t)t * DIM;
    float s = 0.f;
    for (int d = threadIdx.x; d < DIM; d += 256) { float v = xr[d]; s += v * v; }
    __shared__ float red[256];
    red[threadIdx.x] = s;
    __syncthreads();
    for (int o = 128; o > 0; o >>= 1) {
        if (threadIdx.x < o) red[threadIdx.x] += red[threadIdx.x + o];
        __syncthreads();
    }
    float inv = rsqrtf(red[0] / (float)DIM + 1e-6f);
    for (int d = threadIdx.x; d < DIM; d += 256) {
        float v = w[d] * xr[d] * inv;
        bf16 h = __float2bfloat16(v);
        size_t idx = (size_t)t * DIM + d;
        hi[idx] = h;
        lo[idx] = __float2bfloat16(v - __bfloat162float(h));
    }
}

// ---------------- bf16 split HMMA GEMM ----------------
// TERMS=3: fp32-ish (A hi+lo, B hi+lo), 3-stage ring.
// TERMS=1: pure bf16 (A hi, B hi), 5-stage ring (deep prefetch).
// EPI: 0=f32(+bias), 1=bf16 out (split if Clo, else hi-only), 2=mix,
//      3=silu(f32 aux)*acc, 4=silu(bf16 auxb)*acc -> bf16 hi
template<int EPI, bool GATHER, bool EXPERT, bool ACAT, int TERMS>
__global__ void __launch_bounds__(256, 2) mma_gemm(
    const bf16* __restrict__ A1h, const bf16* __restrict__ A1l,
    const bf16* __restrict__ A2h, const bf16* __restrict__ A2l, int K1,
    const bf16* __restrict__ Bh_, const bf16* __restrict__ Bl_, size_t strideB,
    const float* __restrict__ bias, const float* __restrict__ aux,
    const bf16* __restrict__ auxb,
    float* __restrict__ C, float* __restrict__ C2,
    bf16* __restrict__ Chi, bf16* __restrict__ Clo,
    int M, int N, int K)
{
    constexpr int NBUF = (TERMS == 3) ? 3 : 5;
    constexpr int STG  = (TERMS == 3) ? STAGE_G3 : STAGE_G1;
    constexpr int BOFF = (TERMS == 3) ? ASZ : APL;

    const bf16* Bh = Bh_;
    const bf16* Bl = Bl_;
    if (EXPERT) {
        int e = g_tile_expert[blockIdx.y];
        if (e < 0) return;
        Bh += (size_t)e * strideB;
        if (TERMS == 3) Bl += (size_t)e * strideB;
    }
    extern __shared__ char dsm[];
    __shared__ int toks[128];
    uint32_t sbase = saddr(dsm);
    int tid = threadIdx.x;
    int m0 = blockIdx.y * 128, n0 = blockIdx.x * 128;

    if (GATHER) {
        if (tid < 128) toks[tid] = g_rows_token[m0 + tid];
        __syncthreads();
    }

    int ar = tid >> 1, acn = (tid & 1) * 16;
    int brr = tid >> 3, bcc = (tid & 7) * 16;
    int arow = GATHER ? toks[ar] : (m0 + ar);
    int nst = K >> 5;

    auto load_stage = [&](int s, int buf) {
        int k0 = s << 5;
        const bf16 *pah = A1h, *pal = A1l;
        int lda = K, kl = k0;
        if (ACAT) {
            if (k0 >= K1) { pah = A2h; pal = A2l; lda = K - K1; kl = k0 - K1; }
            else          { lda = K1; }
        }
        const bf16* gah = pah + (size_t)arow * lda + kl + acn;
        uint32_t ab = sbase + buf * STG + (ar * 40 + acn) * 2;
        cp16(ab, gah);             cp16(ab + 16, gah + 8);
        if (TERMS == 3) {
            const bf16* gal = pal + (size_t)arow * lda + kl + acn;
            cp16(ab + APL, gal);   cp16(ab + APL + 16, gal + 8);
        }
        const bf16* gbh = Bh + (size_t)(k0 + brr) * N + n0 + bcc;
        uint32_t bb = sbase + buf * STG + BOFF + (brr * 136 + bcc) * 2;
        cp16(bb, gbh);             cp16(bb + 16, gbh + 8);
        if (TERMS == 3) {
            const bf16* gbl = Bl + (size_t)(k0 + brr) * N + n0 + bcc;
            cp16(bb + BPL, gbl);   cp16(bb + BPL + 16, gbl + 8);
        }
        cp_commit();
    };

    float acc[2][8][4];
    #pragma unroll
    for (int i = 0; i < 2; ++i)
        #pragma unroll
        for (int j = 0; j < 8; ++j)
            #pragma unroll
            for (int q = 0; q < 4; ++q) acc[i][j][q] = 0.f;

    int lane = tid & 31;
    int warp = tid >> 5;
    int wm = (warp >> 1) * 32, wn = (warp & 1) * 64;
    int a_row = lane & 15, a_col = (lane >> 4) * 8;
    int b_krow = (lane & 7) + ((lane >> 3) & 1) * 8;
    int b_nadd = (lane >> 4) * 8;

    #pragma unroll
    for (int p = 0; p < NBUF - 1; ++p)
        if (p < nst) load_stage(p, p);

    for (int s = 0; s < nst; ++s) {
        int buf = s % NBUF;
        int rem = nst - 1 - s;
        if (NBUF == 5) {
            if (rem >= 3)      cp_wait<3>();
            else if (rem == 2) cp_wait<2>();
            else if (rem == 1) cp_wait<1>();
            else               cp_wait<0>();
        } else {
            if (rem >= 1) cp_wait<1>(); else cp_wait<0>();
        }
        __syncthreads();
        if (s + NBUF - 1 < nst) load_stage(s + NBUF - 1, (s + NBUF - 1) % NBUF);

        uint32_t abuf = sbase + buf * STG;
        uint32_t bbuf = abuf + BOFF;
        #pragma unroll
        for (int kk = 0; kk < 2; ++kk) {
            uint32_t Ah[2][4], Al[2][4];
            #pragma unroll
            for (int mt = 0; mt < 2; ++mt) {
                uint32_t aoff = ((wm + mt * 16 + a_row) * 40 + kk * 16 + a_col) * 2;
                ldsm4(abuf + aoff, Ah[mt]);
                if (TERMS == 3) ldsm4(abuf + APL + aoff, Al[mt]);
            }
            #pragma unroll
            for (int half = 0; half < 2; ++half) {
                uint32_t Bhf[4][2], Blf[4][2];
                #pragma unroll
                for (int g16 = 0; g16 < 2; ++g16) {
                    uint32_t boff = ((kk * 16 + b_krow) * 136 + wn + half * 32 + g16 * 16 + b_nadd) * 2;
                    uint32_t r0, r1, r2, r3;
                    ldsm4t(bbuf + boff, r0, r1, r2, r3);
                    Bhf[2 * g16][0] = r0; Bhf[2 * g16][1] = r1;
                    Bhf[2 * g16 + 1][0] = r2; Bhf[2 * g16 + 1][1] = r3;
                    if (TERMS == 3) {
                        ldsm4t(bbuf + BPL + boff, r0, r1, r2, r3);
                        Blf[2 * g16][0] = r0; Blf[2 * g16][1] = r1;
                        Blf[2 * g16 + 1][0] = r2; Blf[2 * g16 + 1][1] = r3;
                    }
                }
                #pragma unroll
                for (int mt = 0; mt < 2; ++mt)
                    #pragma unroll
                    for (int nn = 0; nn < 4; ++nn)
                        mma_bf16(acc[mt][half * 4 + nn], Ah[mt], Bhf[nn]);
                if (TERMS == 3) {
                    #pragma unroll
                    for (int mt = 0; mt < 2; ++mt)
                        #pragma unroll
                        for (int nn = 0; nn < 4; ++nn)
                            mma_bf16(acc[mt][half * 4 + nn], Ah[mt], Blf[nn]);
                    #pragma unroll
                    for (int mt = 0; mt < 2; ++mt)
                        #pragma unroll
                        for (int nn = 0; nn < 4; ++nn)
                            mma_bf16(acc[mt][half * 4 + nn], Al[mt], Bhf[nn]);
                }
            }
        }
    }

    int g = lane >> 2, ti2 = (lane & 3) * 2;
    #pragma unroll
    for (int mt = 0; mt < 2; ++mt) {
        #pragma unroll
        for (int nn = 0; nn < 8; ++nn) {
            int col = n0 + wn + nn * 8 + ti2;
            #pragma unroll
            for (int hf = 0; hf < 2; ++hf) {
                int row = m0 + wm + mt * 16 + g + hf * 8;
                float v0 = acc[mt][nn][2 * hf], v1 = acc[mt][nn][2 * hf + 1];
                size_t idx = (size_t)row * N + col;
                if (EPI == 0) {
                    if (bias) { v0 += bias[col]; v1 += bias[col + 1]; }
                    *(float2*)&C[idx] = make_float2(v0, v1);
                } else if (EPI == 1) {
                    if (Clo) {
                        split_store(Chi, Clo, idx, v0, v1);
                    } else {
                        bf162 h2;
                        h2.x = __float2bfloat16(v0);
                        h2.y = __float2bfloat16(v1);
                        *(bf162*)&Chi[idx] = h2;
                    }
                } else if (EPI == 2) {
                    v0 += bias[col]; v1 += bias[col + 1];
                    *(float2*)&C[idx] = make_float2(v0, v1);
                    float2 r = *(const float2*)&aux[idx];
                    *(float2*)&C2[idx] = make_float2(v0 + r.x, v1 + r.y);
                } else if (EPI == 3) {
                    float2 hv = *(const float2*)&aux[idx];
                    float s0 = hv.x / (1.f + __expf(-hv.x));
                    float s1 = hv.y / (1.f + __expf(-hv.y));
                    float r0 = v0 * s0, r1 = v1 * s1;
                    if (Clo) {
                        split_store(Chi, Clo, idx, r0, r1);
                    } else {
                        bf162 h2;
                        h2.x = __float2bfloat16(r0);
                        h2.y = __float2bfloat16(r1);
                        *(bf162*)&Chi[idx] = h2;
                    }
                } else { // EPI == 4: silu(bf16 aux)*acc -> bf16 hi
                    bf162 hv = *(const bf162*)&auxb[idx];
                    float a0 = __bfloat162float(hv.x), a1 = __bfloat162float(hv.y);
                    float s0 = a0 / (1.f + __expf(-a0));
                    float s1 = a1 / (1.f + __expf(-a1));
                    bf162 h2;
                    h2.x = __float2bfloat16(v0 * s0);
                    h2.y = __float2bfloat16(v1 * s1);
                    *(bf162*)&Chi[idx] = h2;
                }
            }
        }
    }
}

// ---------------- tensor-core attention, Q in smem, 2 CTAs/SM ----------------
__global__ void __launch_bounds__(256, 2) attn_mma(
    const bf16* __restrict__ Qh, const bf16* __restrict__ Ql,
    bf16* __restrict__ Ohi, bf16* __restrict__ Olo)
{
    extern __shared__ char dsm[];
    uint32_t sb = saddr(dsm);
    uint32_t kvbase = sb + ATQ_SZ;
    int b = blockIdx.z, h = blockIdx.y, q0 = blockIdx.x * 128;
    int kvh = h >> 2;
    int tid = threadIdx.x, lane = tid & 31, w = tid >> 5;

    {
        int plane = tid >> 7, row = tid & 127;
        const bf16* src = (plane ? Ql : Qh) + (size_t)(b * SEQ + q0 + row) * QKVN + h * HD;
        uint32_t dst = sb + plane * ATQ_PL + row * 144;
        #pragma unroll
        for (int c = 0; c < 8; ++c) cp16(dst + c * 16, src + c * 8);
        cp_commit();
    }

    auto loadkv = [&](int kt, int buf) {
        int p = tid >> 6, row = tid & 63;
        size_t goff = (size_t)(b * SEQ + kt * 64 + row) * QKVN + DIM + kvh * HD;
        if (p >= 2) goff += NKVH * HD;
        const bf16* src = ((p & 1) ? Ql : Qh) + goff;
        uint32_t dst = kvbase + buf * AT_BUF + p * AT_PL + row * 144;
        #pragma unroll
        for (int c = 0; c < 8; ++c) cp16(dst + c * 16, src + c * 8);
        cp_commit();
    };

    float O[8][4];
    #pragma unroll
    for (int i = 0; i < 8; ++i)
        #pragma unroll
        for (int q = 0; q < 4; ++q) O[i][q] = 0.f;
    float l0 = 0.f, l1 = 0.f;

    int qa_r = lane & 15, qa_c = (lane >> 4) * 8;
    int kb_r = (lane & 7) + ((lane >> 4) & 1) * 8;
    int kb_c = ((lane >> 3) & 1) * 8;
    int vb_r = (lane & 7) + ((lane >> 3) & 1) * 8;
    int vb_c = (lane >> 4) * 8;

    loadkv(0, 0);
    loadkv(1, 1);

    for (int kt = 0; kt < SEQ / 64; ++kt) {
        int buf = kt & 1;
        if (kt + 1 < SEQ / 64) cp_wait<1>(); else cp_wait<0>();
        __syncthreads();
        uint32_t kb = kvbase + buf * AT_BUF;
        uint32_t vb = kb + 2 * AT_PL;

        float s[8][4];
        #pragma unroll
        for (int i = 0; i < 8; ++i)
            #pragma unroll
            for (int q = 0; q < 4; ++q) s[i][q] = 0.f;
        #pragma unroll
        for (int kk = 0; kk < 4; ++kk) {
            uint32_t qh[4], ql[4];
            uint32_t qoff = (uint32_t)((w * 16 + qa_r) * 144 + (kk * 16 + qa_c) * 2);
            ldsm4(sb + qoff, qh);
            ldsm4(sb + ATQ_PL + qoff, ql);
            uint32_t bh[8][2], bl[8][2];
            #pragma unroll
            for (int g2 = 0; g2 < 4; ++g2) {
                uint32_t tmp[4];
                uint32_t off = (uint32_t)((g2 * 16 + kb_r) * 144 + (kk * 16 + kb_c) * 2);
                ldsm4(kb + off, tmp);
                bh[2 * g2][0] = tmp[0]; bh[2 * g2][1] = tmp[1];
                bh[2 * g2 + 1][0] = tmp[2]; bh[2 * g2 + 1][1] = tmp[3];
                ldsm4(kb + AT_PL + off, tmp);
                bl[2 * g2][0] = tmp[0]; bl[2 * g2][1] = tmp[1];
                bl[2 * g2 + 1][0] = tmp[2]; bl[2 * g2 + 1][1] = tmp[3];
            }
            #pragma unroll
            for (int nn = 0; nn < 8; ++nn) mma_bf16(s[nn], qh, bh[nn]);
            #pragma unroll
            for (int nn = 0; nn < 8; ++nn) mma_bf16(s[nn], qh, bl[nn]);
            #pragma unroll
            for (int nn = 0; nn < 8; ++nn) mma_bf16(s[nn], ql, bh[nn]);
        }

        #pragma unroll
        for (int nn = 0; nn < 8; ++nn) {
            #pragma unroll
            for (int q = 0; q < 4; ++q) s[nn][q] = __expf(s[nn][q] * 0.125f);
            l0 += s[nn][0] + s[nn][1];
            l1 += s[nn][2] + s[nn][3];
        }
        uint32_t pah[4][4], pal[4][4];
        #pragma unroll
        for (int kk = 0; kk < 4; ++kk) {
            packsplit(s[2 * kk][0],     s[2 * kk][1],     pah[kk][0], pal[kk][0]);
            packsplit(s[2 * kk][2],     s[2 * kk][3],     pah[kk][1], pal[kk][1]);
            packsplit(s[2 * kk + 1][0], s[2 * kk + 1][1], pah[kk][2], pal[kk][2]);
            packsplit(s[2 * kk + 1][2], s[2 * kk + 1][3], pah[kk][3], pal[kk][3]);
        }

        #pragma unroll
        for (int kk = 0; kk < 4; ++kk) {
            uint32_t vh[8][2], vl[8][2];
            #pragma unroll
            for (int g2 = 0; g2 < 4; ++g2) {
                uint32_t r0, r1, r2, r3;
                uint32_t off = (uint32_t)((kk * 16 + vb_r) * 144 + (g2 * 16 + vb_c) * 2);
                ldsm4t(vb + off, r0, r1, r2, r3);
                vh[2 * g2][0] = r0; vh[2 * g2][1] = r1;
                vh[2 * g2 + 1][0] = r2; vh[2 * g2 + 1][1] = r3;
                ldsm4t(vb + AT_PL + off, r0, r1, r2, r3);
                vl[2 * g2][0] = r0; vl[2 * g2][1] = r1;
                vl[2 * g2 + 1][0] = r2; vl[2 * g2 + 1][1] = r3;
            }
            #pragma unroll
            for (int nn = 0; nn < 8; ++nn) mma_bf16(O[nn], pah[kk], vh[nn]);
            #pragma unroll
            for (int nn = 0; nn < 8; ++nn) mma_bf16(O[nn], pah[kk], vl[nn]);
            #pragma unroll
            for (int nn = 0; nn < 8; ++nn) mma_bf16(O[nn], pal[kk], vh[nn]);
        }
        __syncthreads();
        if (kt + 2 < SEQ / 64) loadkv(kt + 2, buf);
    }

    l0 += __shfl_xor_sync(0xffffffffu, l0, 1);
    l0 += __shfl_xor_sync(0xffffffffu, l0, 2);
    l1 += __shfl_xor_sync(0xffffffffu, l1, 1);
    l1 += __shfl_xor_sync(0xffffffffu, l1, 2);
    float inv0 = 1.f / l0, inv1 = 1.f / l1;

    int g = lane >> 2, t2 = (lane & 3) * 2;
    int row0 = b * SEQ + q0 + w * 16 + g;
    #pragma unroll
    for (int nn = 0; nn < 8; ++nn) {
        int col = h * HD + nn * 8 + t2;
        split_store(Ohi, Olo, (size_t)row0 * DIM + col, O[nn][0] * inv0, O[nn][1] * inv0);
        split_store(Ohi, Olo, (size_t)(row0 + 8) * DIM + col, O[nn][2] * inv1, O[nn][3] * inv1);
    }
}

// ---------------- MoE routing ----------------
__global__ void route_init_kernel() {
    int i = blockIdx.x * 256 + threadIdx.x;
    if (i < MAXR) g_rows_token[i] = 0;
    if (i < NE) { g_cnt[i] = 0; g_fill[i] = 0; }
}

__global__ void gate_kernel(const bf16* __restrict__ hh, const bf16* __restrict__ hl,
                            const float* __restrict__ gw) {
    int t = blockIdx.x;
    int lane = threadIdx.x;
    float p[NE];
    #pragma unroll
    for (int e = 0; e < NE; ++e) p[e] = 0.f;
    size_t base = (size_t)t * DIM;
    for (int d = lane; d < DIM; d += 32) {
        float x = __bfloat162float(hh[base + d]) + __bfloat162float(hl[base + d]);
        const float* g = gw + (size_t)d * NE;
        #pragma unroll
        for (int e = 0; e < NE; ++e) p[e] += x * g[e];
    }
    #pragma unroll
    for (int o = 16; o; o >>= 1) {
        #pragma unroll
        for (int e = 0; e < NE; ++e) p[e] += __shfl_xor_sync(0xffffffffu, p[e], o);
    }
    if (lane == 0) {
        int i0 = 0; float l0 = p[0];
        for (int e = 1; e < NE; ++e) if (p[e] > l0) { l0 = p[e]; i0 = e; }
        int i1 = -1; float l1 = -1e30f;
        for (int e = 0; e < NE; ++e) if (e != i0 && p[e] > l1) { l1 = p[e]; i1 = e; }
        float w0 = 1.f / (1.f + __expf(l1 - l0));
        float w1 = 1.f - w0;
        g_expsel[2 * t] = i0; g_expsel[2 * t + 1] = i1;
        g_expw[2 * t] = w0;  g_expw[2 * t + 1] = w1;
        atomicAdd(&g_cnt[i0], 1);
        atomicAdd(&g_cnt[i1], 1);
    }
}

__global__ void scan_kernel() {
    int off = 0;
    for (int e = 0; e < NE; ++e) {
        g_pstart[e] = off;
        int pad = (g_cnt[e] + 127) & ~127;
        int t0 = off >> 7;
        off += pad;
        int t1 = off >> 7;
        for (int t = t0; t < t1; ++t) g_tile_expert[t] = e;
    }
    for (int t = off >> 7; t < MAXTILES; ++t) g_tile_expert[t] = -1;
}

__global__ void scatter_kernel() {
    int t = blockIdx.x * 256 + threadIdx.x;
    if (t >= T_TOK) return;
    #pragma unroll
    for (int slot = 0; slot < 2; ++slot) {
        int e = g_expsel[2 * t + slot];
        int pos = g_pstart[e] + atomicAdd(&g_fill[e], 1);
        g_rows_token[pos] = t;
        g_tok_rowpos[2 * t + slot] = pos;
    }
}

// ---------------- combine ----------------
__global__ void combine_kernel(const float* __restrict__ h1, float* __restrict__ out,
                               bf16* __restrict__ ohi, bf16* __restrict__ olo) {
    int t = blockIdx.x;
    int r0 = g_tok_rowpos[2 * t], r1 = g_tok_rowpos[2 * t + 1];
    float w0 = g_expw[2 * t], w1 = g_expw[2 * t + 1];
    const float* a  = h1 + (size_t)t * DIM;
    const float* p0 = g_moe + (size_t)r0 * DIM;
    const float* p1 = g_moe + (size_t)r1 * DIM;
    size_t base = (size_t)t * DIM;
    for (int d = threadIdx.x * 4; d < DIM; d += 256 * 4) {
        float4 va = *(const float4*)&a[d];
        float4 v0 = *(const float4*)&p0[d];
        float4 v1 = *(const float4*)&p1[d];
        float4 v;
        v.x = va.x + w0 * v0.x + w1 * v1.x;
        v.y = va.y + w0 * v0.y + w1 * v1.y;
        v.z = va.z + w0 * v0.z + w1 * v1.z;
        v.w = va.w + w0 * v0.w + w1 * v1.w;
        *(float4*)&out[base + d] = v;
        split4_store(ohi, olo, base + d, v);
    }
}

// ---------------- launch ----------------
static inline int cdiv(int a, int b) { return (a + b - 1) / b; }

extern "C" void kernel_launch(void* const* d_in, const int* in_sizes, int n_in,
                              void* d_out, int out_size) {
    const float* hidden = (const float*)d_in[0];
    const float* prev   = (const float*)d_in[2];
    const float* wq     = (const float*)d_in[3];
    const float* wk     = (const float*)d_in[4];
    const float* wv     = (const float*)d_in[5];
    const float* wo     = (const float*)d_in[6];
    const float* mix_w  = (const float*)d_in[7];
    const float* mix_b  = (const float*)d_in[8];
    const float* gate_w = (const float*)d_in[9];
    const float* w1     = (const float*)d_in[10];
    const float* w2     = (const float*)d_in[11];
    const float* w3     = (const float*)d_in[12];
    const float* ln1    = (const float*)d_in[13];
    const float* ln2    = (const float*)d_in[14];
    const float* comp_w = (const float*)d_in[15];
    const float* comp_b = (const float*)d_in[16];

    float* out_h     = (float*)d_out;
    float* out_mixed = out_h + (size_t)T_TOK * DIM;
    float* out_comp  = out_mixed + (size_t)T_TOK * DIM;

    float *h1, *moe;
    cudaGetSymbolAddress((void**)&h1, g_h1);
    cudaGetSymbolAddress((void**)&moe, g_moe);
    bf16 *h1bufb, *qxh,*qxl,*xnh,*xnl,*atth,*attl,*prevh,*prevl,*h2h,*h2l,*acth,*outhh,*outhl;
    cudaGetSymbolAddress((void**)&h1bufb, g_h1bufb);
    cudaGetSymbolAddress((void**)&qxh, g_qxh);   cudaGetSymbolAddress((void**)&qxl, g_qxl);
    cudaGetSymbolAddress((void**)&xnh, g_xnh);   cudaGetSymbolAddress((void**)&xnl, g_xnl);
    cudaGetSymbolAddress((void**)&atth, g_atth); cudaGetSymbolAddress((void**)&attl, g_attl);
    cudaGetSymbolAddress((void**)&prevh, g_prevh); cudaGetSymbolAddress((void**)&prevl, g_prevl);
    cudaGetSymbolAddress((void**)&h2h, g_h2h);   cudaGetSymbolAddress((void**)&h2l, g_h2l);
    cudaGetSymbolAddress((void**)&acth, g_acth);
    cudaGetSymbolAddress((void**)&outhh, g_outhh); cudaGetSymbolAddress((void**)&outhl, g_outhl);
    bf16 *wqkvh,*wqkvl,*woh,*wol,*mth,*mtl,*meh,*mel,*w1h,*w2h,*w3h,*cwh,*cwl;
    cudaGetSymbolAddress((void**)&wqkvh, g_wqkvh); cudaGetSymbolAddress((void**)&wqkvl, g_wqkvl);
    cudaGetSymbolAddress((void**)&woh, g_woh);     cudaGetSymbolAddress((void**)&wol, g_wol);
    cudaGetSymbolAddress((void**)&mth, g_mixtoph); cudaGetSymbolAddress((void**)&mtl, g_mixtopl);
    cudaGetSymbolAddress((void**)&meh, g_mixeffh); cudaGetSymbolAddress((void**)&mel, g_mixeffl);
    cudaGetSymbolAddress((void**)&w1h, g_w1h);
    cudaGetSymbolAddress((void**)&w2h, g_w2h);
    cudaGetSymbolAddress((void**)&w3h, g_w3h);
    cudaGetSymbolAddress((void**)&cwh, g_cwh);     cudaGetSymbolAddress((void**)&cwl, g_cwl);

    cudaFuncSetAttribute(mma_gemm<1,false,false,false,3>, cudaFuncAttributeMaxDynamicSharedMemorySize, SMEM_G3);
    cudaFuncSetAttribute(mma_gemm<2,false,false,true,3>,  cudaFuncAttributeMaxDynamicSharedMemorySize, SMEM_G3);
    cudaFuncSetAttribute(mma_gemm<1,true,true,false,1>,   cudaFuncAttributeMaxDynamicSharedMemorySize, SMEM_G1);
    cudaFuncSetAttribute(mma_gemm<4,true,true,false,1>,   cudaFuncAttributeMaxDynamicSharedMemorySize, SMEM_G1);
    cudaFuncSetAttribute(mma_gemm<0,false,true,false,1>,  cudaFuncAttributeMaxDynamicSharedMemorySize, SMEM_G1);
    cudaFuncSetAttribute(mma_gemm<0,false,false,false,3>, cudaFuncAttributeMaxDynamicSharedMemorySize, SMEM_G3);
    cudaFuncSetAttribute(attn_mma, cudaFuncAttributeMaxDynamicSharedMemorySize, SMEM_AT);

    qkvpack_kernel<<<cdiv(DIM * QKVN / 4, 256), 256>>>(wq, wk, wv, wqkvh, wqkvl);
    rmsnorm_split_kernel<<<T_TOK, 256>>>(hidden, ln1, xnh, xnl);

    mma_gemm<1,false,false,false,3><<<dim3(QKVN / 128, T_TOK / 128), 256, SMEM_G3>>>(
        xnh, xnl, nullptr, nullptr, 0, wqkvh, wqkvl, 0,
        nullptr, nullptr, nullptr, nullptr, nullptr, qxh, qxl, T_TOK, QKVN, DIM);

    attn_mma<<<dim3(SEQ / 128, NH, NB), 256, SMEM_AT>>>(qxh, qxl, atth, attl);

    // effective mixer weight: mixeff = [wo @ mix_top ; mix_bot]
    split4_dual_kernel<<<cdiv(DIM * DIM / 4, 256), 256>>>(
        wo, woh, wol, mix_w, mth, mtl, DIM * DIM);
    mma_gemm<1,false,false,false,3><<<dim3(DIM / 128, DIM / 128), 256, SMEM_G3>>>(
        woh, wol, nullptr, nullptr, 0, mth, mtl, 0,
        nullptr, nullptr, nullptr, nullptr, nullptr, meh, mel, DIM, DIM, DIM);
    split4_kernel<<<cdiv(DIM * DIM / 4, 256), 256>>>(mix_w + (size_t)DIM * DIM,
                                                     meh + (size_t)DIM * DIM,
                                                     mel + (size_t)DIM * DIM, DIM * DIM);
    split4_kernel<<<cdiv(T_TOK * DIM / 4, 256), 256>>>(prev, prevh, prevl, T_TOK * DIM);

    mma_gemm<2,false,false,true,3><<<dim3(DIM / 128, T_TOK / 128), 256, SMEM_G3>>>(
        atth, attl, prevh, prevl, DIM, meh, mel, 0,
        mix_b, hidden, nullptr, out_mixed, h1, nullptr, nullptr, T_TOK, DIM, 2 * DIM);

    rmsnorm_split_kernel<<<T_TOK, 256>>>(h1, ln2, h2h, h2l);

    route_init_kernel<<<cdiv(MAXR, 256), 256>>>();
    gate_kernel<<<T_TOK, 32>>>(h2h, h2l, gate_w);
    scan_kernel<<<1, 1>>>();
    scatter_kernel<<<T_TOK / 256, 256>>>();

    cvt4_dual_kernel<<<cdiv(NE * DIM * FF / 4, 256), 256>>>(w1, w1h, w3, w3h, NE * DIM * FF);

    // MoE pure-bf16 (TERMS=1, K-step 32, 5-stage ring; bf16 intermediate)
    mma_gemm<1,true,true,false,1><<<dim3(FF / 128, MAXTILES), 256, SMEM_G1>>>(
        h2h, nullptr, nullptr, nullptr, 0, w1h, nullptr, (size_t)DIM * FF,
        nullptr, nullptr, nullptr, nullptr, nullptr, h1bufb, nullptr, MAXR, FF, DIM);

    mma_gemm<4,true,true,false,1><<<dim3(FF / 128, MAXTILES), 256, SMEM_G1>>>(
        h2h, nullptr, nullptr, nullptr, 0, w3h, nullptr, (size_t)DIM * FF,
        nullptr, nullptr, h1bufb, nullptr, nullptr, acth, nullptr, MAXR, FF, DIM);

    cvt4_kernel<<<cdiv(NE * FF * DIM / 4, 256), 256>>>(w2, w2h, NE * FF * DIM);

    mma_gemm<0,false,true,false,1><<<dim3(DIM / 128, MAXTILES), 256, SMEM_G1>>>(
        acth, nullptr, nullptr, nullptr, 0, w2h, nullptr, (size_t)FF * DIM,
        nullptr, nullptr, nullptr, moe, nullptr, nullptr, nullptr, MAXR, DIM, FF);

    combine_kernel<<<T_TOK, 256>>>(h1, out_h, outhh, outhl);

    split4_kernel<<<cdiv(DIM * NCOMP / 4, 256), 256>>>(comp_w, cwh, cwl, DIM * NCOMP);

    mma_gemm<0,false,false,false,3><<<dim3(NCOMP / 128, T_TOK / 128), 256, SMEM_G3>>>(
        outhh, outhl, nullptr, nullptr, 0, cwh, cwl, 0,
        comp_b, nullptr, nullptr, out_comp, nullptr, nullptr, nullptr, T_TOK, NCOMP, DIM);
}

// round 17
// speedup vs baseline: 1.2883x; 1.1560x over previous
#include <cuda_runtime.h>
#include <cuda_bf16.h>
#include <math.h>
#include <stdint.h>

// ---------------- problem constants ----------------
#define T_TOK 4096
#define DIM   1024
#define SEQ   1024
#define NB    4
#define NH    16
#define NKVH  4
#define HD    64
#define NE    8
#define FF    2816
#define NCOMP 256
#define QKVN  1536
#define MAXR  9216
#define MAXTILES 72

typedef __nv_bfloat16 bf16;
typedef __nv_bfloat162 bf162;

struct bf16x4 { bf162 a, b; };

// ---------------- scratch (device globals) ----------------
__device__ float g_h1[(size_t)T_TOK * DIM];
__device__ float g_moe[(size_t)MAXR * DIM];

__device__ bf16 g_h1bufb[(size_t)MAXR * FF];
__device__ bf16 g_qxh[(size_t)T_TOK * QKVN];           // hi-only qkv
__device__ bf16 g_xnh[(size_t)T_TOK * DIM];            // hi-only ln1 out
__device__ bf16 g_atth[(size_t)T_TOK * DIM], g_attl[(size_t)T_TOK * DIM];
__device__ bf16 g_prevh[(size_t)T_TOK * DIM],g_prevl[(size_t)T_TOK * DIM];
__device__ bf16 g_h2h[(size_t)T_TOK * DIM],  g_h2l[(size_t)T_TOK * DIM];
__device__ bf16 g_acth[(size_t)MAXR * FF];
__device__ bf16 g_outhh[(size_t)T_TOK * DIM],g_outhl[(size_t)T_TOK * DIM];

// weights [K][N] layout
__device__ bf16 g_wqkvh[(size_t)DIM * QKVN];           // hi-only
__device__ bf16 g_woh[(size_t)DIM * DIM],    g_wol[(size_t)DIM * DIM];
__device__ bf16 g_mixtoph[(size_t)DIM * DIM], g_mixtopl[(size_t)DIM * DIM];
__device__ bf16 g_mixeffh[(size_t)2 * DIM * DIM], g_mixeffl[(size_t)2 * DIM * DIM];
__device__ bf16 g_w1h[(size_t)NE * DIM * FF];
__device__ bf16 g_w2h[(size_t)NE * FF * DIM];
__device__ bf16 g_w3h[(size_t)NE * DIM * FF];
__device__ bf16 g_cwh[(size_t)DIM * NCOMP],  g_cwl[(size_t)DIM * NCOMP];

__device__ int   g_expsel[T_TOK * 2];
__device__ float g_expw[T_TOK * 2];
__device__ int   g_cnt[NE];
__device__ int   g_fill[NE];
__device__ int   g_pstart[NE];
__device__ int   g_rows_token[MAXR];
__device__ int   g_tok_rowpos[T_TOK * 2];
__device__ int   g_tile_expert[MAXTILES];

// ---------------- asm helpers ----------------
__device__ __forceinline__ uint32_t saddr(const void* p) {
    return (uint32_t)__cvta_generic_to_shared(p);
}
__device__ __forceinline__ void cp16(uint32_t s, const void* g) {
    asm volatile("cp.async.cg.shared.global [%0], [%1], 16;\n" :: "r"(s), "l"(g));
}
__device__ __forceinline__ void cp_commit() { asm volatile("cp.async.commit_group;\n"); }
template<int N> __device__ __forceinline__ void cp_wait() {
    asm volatile("cp.async.wait_group %0;\n" :: "n"(N));
}
__device__ __forceinline__ void ldsm4(uint32_t a, uint32_t* r) {
    asm volatile("ldmatrix.sync.aligned.m8n8.x4.shared.b16 {%0,%1,%2,%3}, [%4];\n"
                 : "=r"(r[0]), "=r"(r[1]), "=r"(r[2]), "=r"(r[3]) : "r"(a));
}
__device__ __forceinline__ void ldsm4t(uint32_t a, uint32_t& r0, uint32_t& r1, uint32_t& r2, uint32_t& r3) {
    asm volatile("ldmatrix.sync.aligned.m8n8.x4.trans.shared.b16 {%0,%1,%2,%3}, [%4];\n"
                 : "=r"(r0), "=r"(r1), "=r"(r2), "=r"(r3) : "r"(a));
}
__device__ __forceinline__ void mma_bf16(float c[4], const uint32_t a[4], const uint32_t b[2]) {
    asm volatile("mma.sync.aligned.m16n8k16.row.col.f32.bf16.bf16.f32 "
                 "{%0,%1,%2,%3}, {%4,%5,%6,%7}, {%8,%9}, {%0,%1,%2,%3};\n"
                 : "+f"(c[0]), "+f"(c[1]), "+f"(c[2]), "+f"(c[3])
                 : "r"(a[0]), "r"(a[1]), "r"(a[2]), "r"(a[3]), "r"(b[0]), "r"(b[1]));
}

// ---------------- smem geometry (GEMM) ----------------
#define APL (128 * 40 * 2)
#define ASZ (2 * APL)
#define BPL (32 * 136 * 2)
#define BSZ (2 * BPL)
#define STAGE_G3 (ASZ + BSZ)        // 37888  (TERMS=3, 3 stages)
#define SMEM_G3  (3 * STAGE_G3)
#define STAGE_G1 (APL + BPL)        // 18944  (TERMS=1, 5 stages)
#define SMEM_G1  (5 * STAGE_G1)     // 94720 -> 2 CTAs/SM

// attention smem (1-term): Q hi (128x144) + 2 bufs x (K,V hi) x (64x144)
#define AT1Q_PL 18432
#define AT1_PL  9216
#define AT1_BUF (2 * AT1_PL)        // 18432
#define SMEM_AT1 (AT1Q_PL + 2 * AT1_BUF)  // 55296 -> 2 CTAs/SM

// ---------------- split helpers ----------------
__device__ __forceinline__ void split_store(bf16* hi, bf16* lo, size_t idx, float v0, float v1) {
    bf162 h2, l2;
    h2.x = __float2bfloat16(v0); h2.y = __float2bfloat16(v1);
    l2.x = __float2bfloat16(v0 - __bfloat162float(h2.x));
    l2.y = __float2bfloat16(v1 - __bfloat162float(h2.y));
    *(bf162*)&hi[idx] = h2;
    *(bf162*)&lo[idx] = l2;
}
__device__ __forceinline__ void split4_store(bf16* hi, bf16* lo, size_t idx, float4 v) {
    bf16x4 h, l;
    h.a.x = __float2bfloat16(v.x); h.a.y = __float2bfloat16(v.y);
    h.b.x = __float2bfloat16(v.z); h.b.y = __float2bfloat16(v.w);
    l.a.x = __float2bfloat16(v.x - __bfloat162float(h.a.x));
    l.a.y = __float2bfloat16(v.y - __bfloat162float(h.a.y));
    l.b.x = __float2bfloat16(v.z - __bfloat162float(h.b.x));
    l.b.y = __float2bfloat16(v.w - __bfloat162float(h.b.y));
    *(bf16x4*)&hi[idx] = h;
    *(bf16x4*)&lo[idx] = l;
}
__device__ __forceinline__ void cvt4_store(bf16* dst, size_t idx, float4 v) {
    bf16x4 h;
    h.a.x = __float2bfloat16(v.x); h.a.y = __float2bfloat16(v.y);
    h.b.x = __float2bfloat16(v.z); h.b.y = __float2bfloat16(v.w);
    *(bf16x4*)&dst[idx] = h;
}
__device__ __forceinline__ uint32_t pack2(float v0, float v1) {
    bf162 h;
    h.x = __float2bfloat16(v0); h.y = __float2bfloat16(v1);
    return *(uint32_t*)&h;
}

__global__ void split4_kernel(const float* __restrict__ src, bf16* __restrict__ hi,
                              bf16* __restrict__ lo, int n) {
    int i = (blockIdx.x * 256 + threadIdx.x) * 4;
    if (i >= n) return;
    split4_store(hi, lo, i, *(const float4*)(src + i));
}

__global__ void split4_dual_kernel(const float* __restrict__ s1, bf16* __restrict__ h1,
                                   bf16* __restrict__ l1, const float* __restrict__ s3,
                                   bf16* __restrict__ h3, bf16* __restrict__ l3, int n) {
    int i = (blockIdx.x * 256 + threadIdx.x) * 4;
    if (i >= n) return;
    split4_store(h1, l1, i, *(const float4*)(s1 + i));
    split4_store(h3, l3, i, *(const float4*)(s3 + i));
}

__global__ void cvt4_dual_kernel(const float* __restrict__ s1, bf16* __restrict__ d1,
                                 const float* __restrict__ s3, bf16* __restrict__ d3, int n) {
    int i = (blockIdx.x * 256 + threadIdx.x) * 4;
    if (i >= n) return;
    cvt4_store(d1, i, *(const float4*)(s1 + i));
    cvt4_store(d3, i, *(const float4*)(s3 + i));
}

__global__ void cvt4_kernel(const float* __restrict__ src, bf16* __restrict__ dst, int n) {
    int i = (blockIdx.x * 256 + threadIdx.x) * 4;
    if (i >= n) return;
    cvt4_store(dst, i, *(const float4*)(src + i));
}

// hi-only packed wq|wk|wv
__global__ void qkvpack_cvt_kernel(const float* __restrict__ wq, const float* __restrict__ wk,
                                   const float* __restrict__ wv, bf16* __restrict__ hi) {
    int i = (blockIdx.x * 256 + threadIdx.x) * 4;
    if (i >= DIM * QKVN) return;
    int r = i / QKVN, c = i % QKVN;
    float4 v;
    if (c < 1024)      v = *(const float4*)(wq + (size_t)r * 1024 + c);
    else if (c < 1280) v = *(const float4*)(wk + (size_t)r * 256 + (c - 1024));
    else               v = *(const float4*)(wv + (size_t)r * 256 + (c - 1280));
    cvt4_store(hi, i, v);
}

// ---------------- RMSNorm ----------------
__global__ void rmsnorm_split_kernel(const float* __restrict__ x, const float* __restrict__ w,
                                     bf16* __restrict__ hi, bf16* __restrict__ lo) {
    int t = blockIdx.x;
    const float* xr = x + (size_t)t * DIM;
    float s = 0.f;
    for (int d = threadIdx.x; d < DIM; d += 256) { float v = xr[d]; s += v * v; }
    __shared__ float red[256];
    red[threadIdx.x] = s;
    __syncthreads();
    for (int o = 128; o > 0; o >>= 1) {
        if (threadIdx.x < o) red[threadIdx.x] += red[threadIdx.x + o];
        __syncthreads();
    }
    float inv = rsqrtf(red[0] / (float)DIM + 1e-6f);
    for (int d = threadIdx.x; d < DIM; d += 256) {
        float v = w[d] * xr[d] * inv;
        bf16 h = __float2bfloat16(v);
        size_t idx = (size_t)t * DIM + d;
        hi[idx] = h;
        lo[idx] = __float2bfloat16(v - __bfloat162float(h));
    }
}

__global__ void rmsnorm_cvt_kernel(const float* __restrict__ x, const float* __restrict__ w,
                                   bf16* __restrict__ hi) {
    int t = blockIdx.x;
    const float* xr = x + (size_t)t * DIM;
    float s = 0.f;
    for (int d = threadIdx.x; d < DIM; d += 256) { float v = xr[d]; s += v * v; }
    __shared__ float red[256];
    red[threadIdx.x] = s;
    __syncthreads();
    for (int o = 128; o > 0; o >>= 1) {
        if (threadIdx.x < o) red[threadIdx.x] += red[threadIdx.x + o];
        __syncthreads();
    }
    float inv = rsqrtf(red[0] / (float)DIM + 1e-6f);
    for (int d = threadIdx.x; d < DIM; d += 256)
        hi[(size_t)t * DIM + d] = __float2bfloat16(w[d] * xr[d] * inv);
}

// ---------------- bf16 split HMMA GEMM ----------------
// TERMS=3: A hi+lo, B hi+lo, 3-stage ring. TERMS=1: A hi, B hi, 5-stage ring.
// EPI: 0=f32(+bias), 1=bf16 out (split if Clo, else hi-only), 2=mix,
//      4=silu(bf16 auxb)*acc -> bf16 hi
template<int EPI, bool GATHER, bool EXPERT, bool ACAT, int TERMS>
__global__ void __launch_bounds__(256, 2) mma_gemm(
    const bf16* __restrict__ A1h, const bf16* __restrict__ A1l,
    const bf16* __restrict__ A2h, const bf16* __restrict__ A2l, int K1,
    const bf16* __restrict__ Bh_, const bf16* __restrict__ Bl_, size_t strideB,
    const float* __restrict__ bias, const float* __restrict__ aux,
    const bf16* __restrict__ auxb,
    float* __restrict__ C, float* __restrict__ C2,
    bf16* __restrict__ Chi, bf16* __restrict__ Clo,
    int M, int N, int K)
{
    constexpr int NBUF = (TERMS == 3) ? 3 : 5;
    constexpr int STG  = (TERMS == 3) ? STAGE_G3 : STAGE_G1;
    constexpr int BOFF = (TERMS == 3) ? ASZ : APL;

    const bf16* Bh = Bh_;
    const bf16* Bl = Bl_;
    if (EXPERT) {
        int e = g_tile_expert[blockIdx.y];
        if (e < 0) return;
        Bh += (size_t)e * strideB;
        if (TERMS == 3) Bl += (size_t)e * strideB;
    }
    extern __shared__ char dsm[];
    __shared__ int toks[128];
    uint32_t sbase = saddr(dsm);
    int tid = threadIdx.x;
    int m0 = blockIdx.y * 128, n0 = blockIdx.x * 128;

    if (GATHER) {
        if (tid < 128) toks[tid] = g_rows_token[m0 + tid];
        __syncthreads();
    }

    int ar = tid >> 1, acn = (tid & 1) * 16;
    int brr = tid >> 3, bcc = (tid & 7) * 16;
    int arow = GATHER ? toks[ar] : (m0 + ar);
    int nst = K >> 5;

    auto load_stage = [&](int s, int buf) {
        int k0 = s << 5;
        const bf16 *pah = A1h, *pal = A1l;
        int lda = K, kl = k0;
        if (ACAT) {
            if (k0 >= K1) { pah = A2h; pal = A2l; lda = K - K1; kl = k0 - K1; }
            else          { lda = K1; }
        }
        const bf16* gah = pah + (size_t)arow * lda + kl + acn;
        uint32_t ab = sbase + buf * STG + (ar * 40 + acn) * 2;
        cp16(ab, gah);             cp16(ab + 16, gah + 8);
        if (TERMS == 3) {
            const bf16* gal = pal + (size_t)arow * lda + kl + acn;
            cp16(ab + APL, gal);   cp16(ab + APL + 16, gal + 8);
        }
        const bf16* gbh = Bh + (size_t)(k0 + brr) * N + n0 + bcc;
        uint32_t bb = sbase + buf * STG + BOFF + (brr * 136 + bcc) * 2;
        cp16(bb, gbh);             cp16(bb + 16, gbh + 8);
        if (TERMS == 3) {
            const bf16* gbl = Bl + (size_t)(k0 + brr) * N + n0 + bcc;
            cp16(bb + BPL, gbl);   cp16(bb + BPL + 16, gbl + 8);
        }
        cp_commit();
    };

    float acc[2][8][4];
    #pragma unroll
    for (int i = 0; i < 2; ++i)
        #pragma unroll
        for (int j = 0; j < 8; ++j)
            #pragma unroll
            for (int q = 0; q < 4; ++q) acc[i][j][q] = 0.f;

    int lane = tid & 31;
    int warp = tid >> 5;
    int wm = (warp >> 1) * 32, wn = (warp & 1) * 64;
    int a_row = lane & 15, a_col = (lane >> 4) * 8;
    int b_krow = (lane & 7) + ((lane >> 3) & 1) * 8;
    int b_nadd = (lane >> 4) * 8;

    #pragma unroll
    for (int p = 0; p < NBUF - 1; ++p)
        if (p < nst) load_stage(p, p);

    for (int s = 0; s < nst; ++s) {
        int buf = s % NBUF;
        int rem = nst - 1 - s;
        if (NBUF == 5) {
            if (rem >= 3)      cp_wait<3>();
            else if (rem == 2) cp_wait<2>();
            else if (rem == 1) cp_wait<1>();
            else               cp_wait<0>();
        } else {
            if (rem >= 1) cp_wait<1>(); else cp_wait<0>();
        }
        __syncthreads();
        if (s + NBUF - 1 < nst) load_stage(s + NBUF - 1, (s + NBUF - 1) % NBUF);

        uint32_t abuf = sbase + buf * STG;
        uint32_t bbuf = abuf + BOFF;
        #pragma unroll
        for (int kk = 0; kk < 2; ++kk) {
            uint32_t Ah[2][4], Al[2][4];
            #pragma unroll
            for (int mt = 0; mt < 2; ++mt) {
                uint32_t aoff = ((wm + mt * 16 + a_row) * 40 + kk * 16 + a_col) * 2;
                ldsm4(abuf + aoff, Ah[mt]);
                if (TERMS == 3) ldsm4(abuf + APL + aoff, Al[mt]);
            }
            #pragma unroll
            for (int half = 0; half < 2; ++half) {
                uint32_t Bhf[4][2], Blf[4][2];
                #pragma unroll
                for (int g16 = 0; g16 < 2; ++g16) {
                    uint32_t boff = ((kk * 16 + b_krow) * 136 + wn + half * 32 + g16 * 16 + b_nadd) * 2;
                    uint32_t r0, r1, r2, r3;
                    ldsm4t(bbuf + boff, r0, r1, r2, r3);
                    Bhf[2 * g16][0] = r0; Bhf[2 * g16][1] = r1;
                    Bhf[2 * g16 + 1][0] = r2; Bhf[2 * g16 + 1][1] = r3;
                    if (TERMS == 3) {
                        ldsm4t(bbuf + BPL + boff, r0, r1, r2, r3);
                        Blf[2 * g16][0] = r0; Blf[2 * g16][1] = r1;
                        Blf[2 * g16 + 1][0] = r2; Blf[2 * g16 + 1][1] = r3;
                    }
                }
                #pragma unroll
                for (int mt = 0; mt < 2; ++mt)
                    #pragma unroll
                    for (int nn = 0; nn < 4; ++nn)
                        mma_bf16(acc[mt][half * 4 + nn], Ah[mt], Bhf[nn]);
                if (TERMS == 3) {
                    #pragma unroll
                    for (int mt = 0; mt < 2; ++mt)
                        #pragma unroll
                        for (int nn = 0; nn < 4; ++nn)
                            mma_bf16(acc[mt][half * 4 + nn], Ah[mt], Blf[nn]);
                    #pragma unroll
                    for (int mt = 0; mt < 2; ++mt)
                        #pragma unroll
                        for (int nn = 0; nn < 4; ++nn)
                            mma_bf16(acc[mt][half * 4 + nn], Al[mt], Bhf[nn]);
                }
            }
        }
    }

    int g = lane >> 2, ti2 = (lane & 3) * 2;
    #pragma unroll
    for (int mt = 0; mt < 2; ++mt) {
        #pragma unroll
        for (int nn = 0; nn < 8; ++nn) {
            int col = n0 + wn + nn * 8 + ti2;
            #pragma unroll
            for (int hf = 0; hf < 2; ++hf) {
                int row = m0 + wm + mt * 16 + g + hf * 8;
                float v0 = acc[mt][nn][2 * hf], v1 = acc[mt][nn][2 * hf + 1];
                size_t idx = (size_t)row * N + col;
                if (EPI == 0) {
                    if (bias) { v0 += bias[col]; v1 += bias[col + 1]; }
                    *(float2*)&C[idx] = make_float2(v0, v1);
                } else if (EPI == 1) {
                    if (Clo) {
                        split_store(Chi, Clo, idx, v0, v1);
                    } else {
                        *(uint32_t*)&Chi[idx] = pack2(v0, v1);
                    }
                } else if (EPI == 2) {
                    v0 += bias[col]; v1 += bias[col + 1];
                    *(float2*)&C[idx] = make_float2(v0, v1);
                    float2 r = *(const float2*)&aux[idx];
                    *(float2*)&C2[idx] = make_float2(v0 + r.x, v1 + r.y);
                } else { // EPI == 4: silu(bf16 aux)*acc -> bf16 hi
                    bf162 hv = *(const bf162*)&auxb[idx];
                    float a0 = __bfloat162float(hv.x), a1 = __bfloat162float(hv.y);
                    float s0 = a0 / (1.f + __expf(-a0));
                    float s1 = a1 / (1.f + __expf(-a1));
                    *(uint32_t*)&Chi[idx] = pack2(v0 * s0, v1 * s1);
                }
            }
        }
    }
}

// ---------------- 1-term tensor-core attention (pure bf16, Q in smem) -------
__global__ void __launch_bounds__(256, 2) attn_mma1(
    const bf16* __restrict__ Qh,
    bf16* __restrict__ Ohi, bf16* __restrict__ Olo)
{
    extern __shared__ char dsm[];
    uint32_t sb = saddr(dsm);
    uint32_t kvbase = sb + AT1Q_PL;
    int b = blockIdx.z, h = blockIdx.y, q0 = blockIdx.x * 128;
    int kvh = h >> 2;
    int tid = threadIdx.x, lane = tid & 31, w = tid >> 5;

    // stage Q hi (persistent): 2 threads/row, 64B each
    {
        int row = tid >> 1, half = tid & 1;
        const bf16* src = Qh + (size_t)(b * SEQ + q0 + row) * QKVN + h * HD + half * 32;
        uint32_t dst = sb + row * 144 + half * 64;
        #pragma unroll
        for (int c = 0; c < 4; ++c) cp16(dst + c * 16, src + c * 8);
        cp_commit();
    }

    // K/V hi loader: p 0=K 1=V, 2 threads/row
    auto loadkv = [&](int kt, int buf) {
        int p = tid >> 7, rr = (tid & 127) >> 1, half = tid & 1;
        size_t goff = (size_t)(b * SEQ + kt * 64 + rr) * QKVN + DIM + kvh * HD + half * 32;
        if (p) goff += NKVH * HD;
        const bf16* src = Qh + goff;
        uint32_t dst = kvbase + buf * AT1_BUF + p * AT1_PL + rr * 144 + half * 64;
        #pragma unroll
        for (int c = 0; c < 4; ++c) cp16(dst + c * 16, src + c * 8);
        cp_commit();
    };

    float O[8][4];
    #pragma unroll
    for (int i = 0; i < 8; ++i)
        #pragma unroll
        for (int q = 0; q < 4; ++q) O[i][q] = 0.f;
    float l0 = 0.f, l1 = 0.f;

    int qa_r = lane & 15, qa_c = (lane >> 4) * 8;
    int kb_r = (lane & 7) + ((lane >> 4) & 1) * 8;
    int kb_c = ((lane >> 3) & 1) * 8;
    int vb_r = (lane & 7) + ((lane >> 3) & 1) * 8;
    int vb_c = (lane >> 4) * 8;

    loadkv(0, 0);
    loadkv(1, 1);

    for (int kt = 0; kt < SEQ / 64; ++kt) {
        int buf = kt & 1;
        if (kt + 1 < SEQ / 64) cp_wait<1>(); else cp_wait<0>();
        __syncthreads();
        uint32_t kb = kvbase + buf * AT1_BUF;
        uint32_t vb = kb + AT1_PL;

        float s[8][4];
        #pragma unroll
        for (int i = 0; i < 8; ++i)
            #pragma unroll
            for (int q = 0; q < 4; ++q) s[i][q] = 0.f;
        #pragma unroll
        for (int kk = 0; kk < 4; ++kk) {
            uint32_t qf[4];
            uint32_t qoff = (uint32_t)((w * 16 + qa_r) * 144 + (kk * 16 + qa_c) * 2);
            ldsm4(sb + qoff, qf);
            uint32_t bh[8][2];
            #pragma unroll
            for (int g2 = 0; g2 < 4; ++g2) {
                uint32_t tmp[4];
                uint32_t off = (uint32_t)((g2 * 16 + kb_r) * 144 + (kk * 16 + kb_c) * 2);
                ldsm4(kb + off, tmp);
                bh[2 * g2][0] = tmp[0]; bh[2 * g2][1] = tmp[1];
                bh[2 * g2 + 1][0] = tmp[2]; bh[2 * g2 + 1][1] = tmp[3];
            }
            #pragma unroll
            for (int nn = 0; nn < 8; ++nn) mma_bf16(s[nn], qf, bh[nn]);
        }

        #pragma unroll
        for (int nn = 0; nn < 8; ++nn) {
            #pragma unroll
            for (int q = 0; q < 4; ++q) s[nn][q] = __expf(s[nn][q] * 0.125f);
            l0 += s[nn][0] + s[nn][1];
            l1 += s[nn][2] + s[nn][3];
        }
        uint32_t pa[4][4];
        #pragma unroll
        for (int kk = 0; kk < 4; ++kk) {
            pa[kk][0] = pack2(s[2 * kk][0],     s[2 * kk][1]);
            pa[kk][1] = pack2(s[2 * kk][2],     s[2 * kk][3]);
            pa[kk][2] = pack2(s[2 * kk + 1][0], s[2 * kk + 1][1]);
            pa[kk][3] = pack2(s[2 * kk + 1][2], s[2 * kk + 1][3]);
        }

        #pragma unroll
        for (int kk = 0; kk < 4; ++kk) {
            uint32_t vh[8][2];
            #pragma unroll
            for (int g2 = 0; g2 < 4; ++g2) {
                uint32_t r0, r1, r2, r3;
                uint32_t off = (uint32_t)((kk * 16 + vb_r) * 144 + (g2 * 16 + vb_c) * 2);
                ldsm4t(vb + off, r0, r1, r2, r3);
                vh[2 * g2][0] = r0; vh[2 * g2][1] = r1;
                vh[2 * g2 + 1][0] = r2; vh[2 * g2 + 1][1] = r3;
            }
            #pragma unroll
            for (int nn = 0; nn < 8; ++nn) mma_bf16(O[nn], pa[kk], vh[nn]);
        }
        __syncthreads();
        if (kt + 2 < SEQ / 64) loadkv(kt + 2, buf);
    }

    l0 += __shfl_xor_sync(0xffffffffu, l0, 1);
    l0 += __shfl_xor_sync(0xffffffffu, l0, 2);
    l1 += __shfl_xor_sync(0xffffffffu, l1, 1);
    l1 += __shfl_xor_sync(0xffffffffu, l1, 2);
    float inv0 = 1.f / l0, inv1 = 1.f / l1;

    int g = lane >> 2, t2 = (lane & 3) * 2;
    int row0 = b * SEQ + q0 + w * 16 + g;
    #pragma unroll
    for (int nn = 0; nn < 8; ++nn) {
        int col = h * HD + nn * 8 + t2;
        split_store(Ohi, Olo, (size_t)row0 * DIM + col, O[nn][0] * inv0, O[nn][1] * inv0);
        split_store(Ohi, Olo, (size_t)(row0 + 8) * DIM + col, O[nn][2] * inv1, O[nn][3] * inv1);
    }
}

// ---------------- MoE routing ----------------
__global__ void route_init_kernel() {
    int i = blockIdx.x * 256 + threadIdx.x;
    if (i < MAXR) g_rows_token[i] = 0;
    if (i < NE) { g_cnt[i] = 0; g_fill[i] = 0; }
}

__global__ void gate_kernel(const bf16* __restrict__ hh, const bf16* __restrict__ hl,
                            const float* __restrict__ gw) {
    int t = blockIdx.x;
    int lane = threadIdx.x;
    float p[NE];
    #pragma unroll
    for (int e = 0; e < NE; ++e) p[e] = 0.f;
    size_t base = (size_t)t * DIM;
    for (int d = lane; d < DIM; d += 32) {
        float x = __bfloat162float(hh[base + d]) + __bfloat162float(hl[base + d]);
        const float* g = gw + (size_t)d * NE;
        #pragma unroll
        for (int e = 0; e < NE; ++e) p[e] += x * g[e];
    }
    #pragma unroll
    for (int o = 16; o; o >>= 1) {
        #pragma unroll
        for (int e = 0; e < NE; ++e) p[e] += __shfl_xor_sync(0xffffffffu, p[e], o);
    }
    if (lane == 0) {
        int i0 = 0; float l0 = p[0];
        for (int e = 1; e < NE; ++e) if (p[e] > l0) { l0 = p[e]; i0 = e; }
        int i1 = -1; float l1 = -1e30f;
        for (int e = 0; e < NE; ++e) if (e != i0 && p[e] > l1) { l1 = p[e]; i1 = e; }
        float w0 = 1.f / (1.f + __expf(l1 - l0));
        float w1 = 1.f - w0;
        g_expsel[2 * t] = i0; g_expsel[2 * t + 1] = i1;
        g_expw[2 * t] = w0;  g_expw[2 * t + 1] = w1;
        atomicAdd(&g_cnt[i0], 1);
        atomicAdd(&g_cnt[i1], 1);
    }
}

__global__ void scan_kernel() {
    int off = 0;
    for (int e = 0; e < NE; ++e) {
        g_pstart[e] = off;
        int pad = (g_cnt[e] + 127) & ~127;
        int t0 = off >> 7;
        off += pad;
        int t1 = off >> 7;
        for (int t = t0; t < t1; ++t) g_tile_expert[t] = e;
    }
    for (int t = off >> 7; t < MAXTILES; ++t) g_tile_expert[t] = -1;
}

__global__ void scatter_kernel() {
    int t = blockIdx.x * 256 + threadIdx.x;
    if (t >= T_TOK) return;
    #pragma unroll
    for (int slot = 0; slot < 2; ++slot) {
        int e = g_expsel[2 * t + slot];
        int pos = g_pstart[e] + atomicAdd(&g_fill[e], 1);
        g_rows_token[pos] = t;
        g_tok_rowpos[2 * t + slot] = pos;
    }
}

// ---------------- combine ----------------
__global__ void combine_kernel(const float* __restrict__ h1, float* __restrict__ out,
                               bf16* __restrict__ ohi, bf16* __restrict__ olo) {
    int t = blockIdx.x;
    int r0 = g_tok_rowpos[2 * t], r1 = g_tok_rowpos[2 * t + 1];
    float w0 = g_expw[2 * t], w1 = g_expw[2 * t + 1];
    const float* a  = h1 + (size_t)t * DIM;
    const float* p0 = g_moe + (size_t)r0 * DIM;
    const float* p1 = g_moe + (size_t)r1 * DIM;
    size_t base = (size_t)t * DIM;
    for (int d = threadIdx.x * 4; d < DIM; d += 256 * 4) {
        float4 va = *(const float4*)&a[d];
        float4 v0 = *(const float4*)&p0[d];
        float4 v1 = *(const float4*)&p1[d];
        float4 v;
        v.x = va.x + w0 * v0.x + w1 * v1.x;
        v.y = va.y + w0 * v0.y + w1 * v1.y;
        v.z = va.z + w0 * v0.z + w1 * v1.z;
        v.w = va.w + w0 * v0.w + w1 * v1.w;
        *(float4*)&out[base + d] = v;
        split4_store(ohi, olo, base + d, v);
    }
}

// ---------------- launch ----------------
static inline int cdiv(int a, int b) { return (a + b - 1) / b; }

extern "C" void kernel_launch(void* const* d_in, const int* in_sizes, int n_in,
                              void* d_out, int out_size) {
    const float* hidden = (const float*)d_in[0];
    const float* prev   = (const float*)d_in[2];
    const float* wq     = (const float*)d_in[3];
    const float* wk     = (const float*)d_in[4];
    const float* wv     = (const float*)d_in[5];
    const float* wo     = (const float*)d_in[6];
    const float* mix_w  = (const float*)d_in[7];
    const float* mix_b  = (const float*)d_in[8];
    const float* gate_w = (const float*)d_in[9];
    const float* w1     = (const float*)d_in[10];
    const float* w2     = (const float*)d_in[11];
    const float* w3     = (const float*)d_in[12];
    const float* ln1    = (const float*)d_in[13];
    const float* ln2    = (const float*)d_in[14];
    const float* comp_w = (const float*)d_in[15];
    const float* comp_b = (const float*)d_in[16];

    float* out_h     = (float*)d_out;
    float* out_mixed = out_h + (size_t)T_TOK * DIM;
    float* out_comp  = out_mixed + (size_t)T_TOK * DIM;

    float *h1, *moe;
    cudaGetSymbolAddress((void**)&h1, g_h1);
    cudaGetSymbolAddress((void**)&moe, g_moe);
    bf16 *h1bufb, *qxh,*xnh,*atth,*attl,*prevh,*prevl,*h2h,*h2l,*acth,*outhh,*outhl;
    cudaGetSymbolAddress((void**)&h1bufb, g_h1bufb);
    cudaGetSymbolAddress((void**)&qxh, g_qxh);
    cudaGetSymbolAddress((void**)&xnh, g_xnh);
    cudaGetSymbolAddress((void**)&atth, g_atth); cudaGetSymbolAddress((void**)&attl, g_attl);
    cudaGetSymbolAddress((void**)&prevh, g_prevh); cudaGetSymbolAddress((void**)&prevl, g_prevl);
    cudaGetSymbolAddress((void**)&h2h, g_h2h);   cudaGetSymbolAddress((void**)&h2l, g_h2l);
    cudaGetSymbolAddress((void**)&acth, g_acth);
    cudaGetSymbolAddress((void**)&outhh, g_outhh); cudaGetSymbolAddress((void**)&outhl, g_outhl);
    bf16 *wqkvh,*woh,*wol,*mth,*mtl,*meh,*mel,*w1h,*w2h,*w3h,*cwh,*cwl;
    cudaGetSymbolAddress((void**)&wqkvh, g_wqkvh);
    cudaGetSymbolAddress((void**)&woh, g_woh);     cudaGetSymbolAddress((void**)&wol, g_wol);
    cudaGetSymbolAddress((void**)&mth, g_mixtoph); cudaGetSymbolAddress((void**)&mtl, g_mixtopl);
    cudaGetSymbolAddress((void**)&meh, g_mixeffh); cudaGetSymbolAddress((void**)&mel, g_mixeffl);
    cudaGetSymbolAddress((void**)&w1h, g_w1h);
    cudaGetSymbolAddress((void**)&w2h, g_w2h);
    cudaGetSymbolAddress((void**)&w3h, g_w3h);
    cudaGetSymbolAddress((void**)&cwh, g_cwh);     cudaGetSymbolAddress((void**)&cwl, g_cwl);

    cudaFuncSetAttribute(mma_gemm<1,false,false,false,1>, cudaFuncAttributeMaxDynamicSharedMemorySize, SMEM_G1);
    cudaFuncSetAttribute(mma_gemm<1,false,false,false,3>, cudaFuncAttributeMaxDynamicSharedMemorySize, SMEM_G3);
    cudaFuncSetAttribute(mma_gemm<2,false,false,true,3>,  cudaFuncAttributeMaxDynamicSharedMemorySize, SMEM_G3);
    cudaFuncSetAttribute(mma_gemm<1,true,true,false,1>,   cudaFuncAttributeMaxDynamicSharedMemorySize, SMEM_G1);
    cudaFuncSetAttribute(mma_gemm<4,true,true,false,1>,   cudaFuncAttributeMaxDynamicSharedMemorySize, SMEM_G1);
    cudaFuncSetAttribute(mma_gemm<0,false,true,false,1>,  cudaFuncAttributeMaxDynamicSharedMemorySize, SMEM_G1);
    cudaFuncSetAttribute(mma_gemm<0,false,false,false,3>, cudaFuncAttributeMaxDynamicSharedMemorySize, SMEM_G3);
    cudaFuncSetAttribute(attn_mma1, cudaFuncAttributeMaxDynamicSharedMemorySize, SMEM_AT1);

    qkvpack_cvt_kernel<<<cdiv(DIM * QKVN / 4, 256), 256>>>(wq, wk, wv, wqkvh);
    rmsnorm_cvt_kernel<<<T_TOK, 256>>>(hidden, ln1, xnh);

    // QKV GEMM pure-bf16 (attention path heavily damped by mixer)
    mma_gemm<1,false,false,false,1><<<dim3(QKVN / 128, T_TOK / 128), 256, SMEM_G1>>>(
        xnh, nullptr, nullptr, nullptr, 0, wqkvh, nullptr, 0,
        nullptr, nullptr, nullptr, nullptr, nullptr, qxh, nullptr, T_TOK, QKVN, DIM);

    attn_mma1<<<dim3(SEQ / 128, NH, NB), 256, SMEM_AT1>>>(qxh, atth, attl);

    // effective mixer weight: mixeff = [wo @ mix_top ; mix_bot]  (full precision)
    split4_dual_kernel<<<cdiv(DIM * DIM / 4, 256), 256>>>(
        wo, woh, wol, mix_w, mth, mtl, DIM * DIM);
    mma_gemm<1,false,false,false,3><<<dim3(DIM / 128, DIM / 128), 256, SMEM_G3>>>(
        woh, wol, nullptr, nullptr, 0, mth, mtl, 0,
        nullptr, nullptr, nullptr, nullptr, nullptr, meh, mel, DIM, DIM, DIM);
    split4_kernel<<<cdiv(DIM * DIM / 4, 256), 256>>>(mix_w + (size_t)DIM * DIM,
                                                     meh + (size_t)DIM * DIM,
                                                     mel + (size_t)DIM * DIM, DIM * DIM);
    split4_kernel<<<cdiv(T_TOK * DIM / 4, 256), 256>>>(prev, prevh, prevl, T_TOK * DIM);

    mma_gemm<2,false,false,true,3><<<dim3(DIM / 128, T_TOK / 128), 256, SMEM_G3>>>(
        atth, attl, prevh, prevl, DIM, meh, mel, 0,
        mix_b, hidden, nullptr, out_mixed, h1, nullptr, nullptr, T_TOK, DIM, 2 * DIM);

    rmsnorm_split_kernel<<<T_TOK, 256>>>(h1, ln2, h2h, h2l);

    route_init_kernel<<<cdiv(MAXR, 256), 256>>>();
    gate_kernel<<<T_TOK, 32>>>(h2h, h2l, gate_w);
    scan_kernel<<<1, 1>>>();
    scatter_kernel<<<T_TOK / 256, 256>>>();

    cvt4_dual_kernel<<<cdiv(NE * DIM * FF / 4, 256), 256>>>(w1, w1h, w3, w3h, NE * DIM * FF);

    // MoE pure-bf16 (TERMS=1, K-step 32, 5-stage ring; bf16 intermediate)
    mma_gemm<1,true,true,false,1><<<dim3(FF / 128, MAXTILES), 256, SMEM_G1>>>(
        h2h, nullptr, nullptr, nullptr, 0, w1h, nullptr, (size_t)DIM * FF,
        nullptr, nullptr, nullptr, nullptr, nullptr, h1bufb, nullptr, MAXR, FF, DIM);

    mma_gemm<4,true,true,false,1><<<dim3(FF / 128, MAXTILES), 256, SMEM_G1>>>(
        h2h, nullptr, nullptr, nullptr, 0, w3h, nullptr, (size_t)DIM * FF,
        nullptr, nullptr, h1bufb, nullptr, nullptr, acth, nullptr, MAXR, FF, DIM);

    cvt4_kernel<<<cdiv(NE * FF * DIM / 4, 256), 256>>>(w2, w2h, NE * FF * DIM);

    mma_gemm<0,false,true,false,1><<<dim3(DIM / 128, MAXTILES), 256, SMEM_G1>>>(
        acth, nullptr, nullptr, nullptr, 0, w2h, nullptr, (size_t)FF * DIM,
        nullptr, nullptr, nullptr, moe, nullptr, nullptr, nullptr, MAXR, DIM, FF);

    combine_kernel<<<T_TOK, 256>>>(h1, out_h, outhh, outhl);

    split4_kernel<<<cdiv(DIM * NCOMP / 4, 256), 256>>>(comp_w, cwh, cwl, DIM * NCOMP);

    mma_gemm<0,false,false,false,3><<<dim3(NCOMP / 128, T_TOK / 128), 256, SMEM_G3>>>(
        outhh, outhl, nullptr, nullptr, 0, cwh, cwl, 0,
        comp_b, nullptr, nullptr, out_comp, nullptr, nullptr, nullptr, T_TOK, NCOMP, DIM);
}